// round 5
// baseline (speedup 1.0000x reference)
#include <cuda_runtime.h>
#include <cuda_bf16.h>
#include <math.h>
#include <stdint.h>

#define B_ 2
#define N_ 2048
#define D_ 1024
#define H_ 16
#define DH_ 64
#define SCALE_ 0.125f   /* 64^-0.5, exact power of two */

/* ------------------------------------------------------------------ */
/* device scratch: everything bf16 hi/lo pairs                         */
/* ------------------------------------------------------------------ */
__device__ __nv_bfloat16 g_xh [4096 * 1024], g_xl [4096 * 1024];
__device__ __nv_bfloat16 g_wqh[3072 * 1024], g_wql[3072 * 1024];
__device__ __nv_bfloat16 g_woh[1024 * 1024], g_wol[1024 * 1024];
__device__ __nv_bfloat16 g_qh [B_*H_*N_*DH_], g_ql [B_*H_*N_*DH_];
__device__ __nv_bfloat16 g_kh [B_*H_*N_*DH_], g_kl [B_*H_*N_*DH_];
__device__ __nv_bfloat16 g_vh [B_*H_*N_*DH_], g_vl [B_*H_*N_*DH_];
__device__ __nv_bfloat16 g_aoh[B_*N_*D_],     g_aol[B_*N_*D_];

/* ------------------------------------------------------------------ */
/* helpers                                                             */
/* ------------------------------------------------------------------ */
__device__ __forceinline__ uint32_t smem_u32(const void* p) {
    uint32_t a;
    asm("{ .reg .u64 t; cvta.to.shared.u64 t, %1; cvt.u32.u64 %0, t; }"
        : "=r"(a) : "l"(p));
    return a;
}

__device__ __forceinline__ void ldsm4(uint32_t addr, uint32_t& r0, uint32_t& r1,
                                      uint32_t& r2, uint32_t& r3) {
    asm volatile("ldmatrix.sync.aligned.m8n8.x4.shared.b16 {%0,%1,%2,%3}, [%4];"
                 : "=r"(r0), "=r"(r1), "=r"(r2), "=r"(r3) : "r"(addr));
}

__device__ __forceinline__ void mma16816(float* c,
                                         uint32_t a0, uint32_t a1, uint32_t a2, uint32_t a3,
                                         uint32_t b0, uint32_t b1) {
    asm volatile(
        "mma.sync.aligned.m16n8k16.row.col.f32.bf16.bf16.f32 "
        "{%0,%1,%2,%3}, {%4,%5,%6,%7}, {%8,%9}, {%0,%1,%2,%3};"
        : "+f"(c[0]), "+f"(c[1]), "+f"(c[2]), "+f"(c[3])
        : "r"(a0), "r"(a1), "r"(a2), "r"(a3), "r"(b0), "r"(b1));
}

__device__ __forceinline__ void split2(float x, float y, uint32_t& hi, uint32_t& lo) {
    __nv_bfloat162 h = __floats2bfloat162_rn(x, y);
    float rx = x - __bfloat162float(h.x);
    float ry = y - __bfloat162float(h.y);
    __nv_bfloat162 l = __floats2bfloat162_rn(rx, ry);
    hi = *reinterpret_cast<uint32_t*>(&h);
    lo = *reinterpret_cast<uint32_t*>(&l);
}

__device__ __forceinline__ void cp16(uint32_t saddr, const void* g) {
    asm volatile("cp.async.cg.shared.global [%0], [%1], 16;"
                 :: "r"(saddr), "l"(g) : "memory");
}
__device__ __forceinline__ void cp_commit() {
    asm volatile("cp.async.commit_group;" ::: "memory");
}
template <int NN>
__device__ __forceinline__ void cp_wait() {
    asm volatile("cp.async.wait_group %0;" :: "n"(NN) : "memory");
}

/* ------------------------------------------------------------------ */
/* split kernel: fp32 -> bf16 hi/lo pair                               */
/* ------------------------------------------------------------------ */
__global__ void __launch_bounds__(256)
split_fp32(const float* __restrict__ src, __nv_bfloat16* __restrict__ h,
           __nv_bfloat16* __restrict__ l, int n4)
{
    int i      = blockIdx.x * blockDim.x + threadIdx.x;
    int stride = gridDim.x * blockDim.x;
    for (; i < n4; i += stride) {
        float4 v = reinterpret_cast<const float4*>(src)[i];
        uint32_t h0, l0, h1, l1;
        split2(v.x, v.y, h0, l0);
        split2(v.z, v.w, h1, l1);
        reinterpret_cast<uint2*>(h)[i] = make_uint2(h0, h1);
        reinterpret_cast<uint2*>(l)[i] = make_uint2(l0, l1);
    }
}

/* ------------------------------------------------------------------ */
/* Pipelined HMMA GEMM on pre-split bf16: C = A * W^T.                 */
/* tile 128x128, BK=32, 256 thr (8 warps 4x2), 3-stage cp.async.       */
/* MODE 0: epilogue -> q/k/v hi/lo (q scaled). MODE 1: fp32 C store.   */
/* ------------------------------------------------------------------ */
#define TSTR 40
#define TILE_E (128 * TSTR)          /* elems per array per stage */
#define STAGES 3
#define GEMM_SMEM (STAGES * 4 * TILE_E * 2)   /* 122880 B */

template <int MODE>
__global__ void __launch_bounds__(256)
gemm_bf16(const __nv_bfloat16* __restrict__ Ah, const __nv_bfloat16* __restrict__ Al,
          const __nv_bfloat16* __restrict__ Wh, const __nv_bfloat16* __restrict__ Wl,
          float* __restrict__ C, int K, int Nout)
{
    extern __shared__ __nv_bfloat16 smem[];
    const uint32_t sb = smem_u32(smem);

    const int tid  = threadIdx.x;
    const int lane = tid & 31;
    const int wid  = tid >> 5;
    const int wm   = wid & 3;
    const int wn   = wid >> 2;

    const int m0 = blockIdx.y * 128;
    const int j0 = blockIdx.x * 128;

    const int nchunk = K >> 5;

    /* issue async loads for K-chunk kc into stage buffer */
    auto issue = [&](int kc, int stage) {
        if (kc < nchunk) {
            const uint32_t st = sb + (uint32_t)stage * 4 * TILE_E * 2;
#pragma unroll
            for (int half = 0; half < 2; half++) {
                int c   = tid + half * 256;      /* 0..511 */
                int row = c >> 2;
                int q   = c & 3;
                uint32_t soff = (uint32_t)(row * TSTR + q * 8) * 2;
                size_t ga = (size_t)(m0 + row) * K + kc * 32 + q * 8;
                size_t gw = (size_t)(j0 + row) * K + kc * 32 + q * 8;
                cp16(st + 0 * TILE_E * 2 + soff, Ah + ga);
                cp16(st + 1 * TILE_E * 2 + soff, Al + ga);
                cp16(st + 2 * TILE_E * 2 + soff, Wh + gw);
                cp16(st + 3 * TILE_E * 2 + soff, Wl + gw);
            }
        }
        cp_commit();
    };

    const int arow = wm * 32 + (lane & 15);
    const int acol = (lane >> 4) << 3;
    const int brow = wn * 64 + ((lane & 7) | ((lane & 16) >> 1));
    const int bcol = lane & 8;

    float acc[2][8][4];
#pragma unroll
    for (int i = 0; i < 2; i++)
#pragma unroll
        for (int j = 0; j < 8; j++)
#pragma unroll
            for (int c = 0; c < 4; c++) acc[i][j][c] = 0.f;

    issue(0, 0);
    issue(1, 1);

    for (int kc = 0; kc < nchunk; kc++) {
        cp_wait<STAGES - 2>();
        __syncthreads();
        issue(kc + STAGES - 1, (kc + STAGES - 1) % STAGES);

        const uint32_t st  = sb + (uint32_t)(kc % STAGES) * 4 * TILE_E * 2;
        const uint32_t sAh = st;
        const uint32_t sAl = st + 1 * TILE_E * 2;
        const uint32_t sWh = st + 2 * TILE_E * 2;
        const uint32_t sWl = st + 3 * TILE_E * 2;

#pragma unroll
        for (int ks = 0; ks < 2; ks++) {
            const uint32_t aoff = 2u * ((uint32_t)(arow * TSTR) + ks * 16 + acol);
            uint32_t ah[2][4], al[2][4];
#pragma unroll
            for (int mt = 0; mt < 2; mt++) {
                uint32_t d = aoff + 2u * (mt * 16 * TSTR);
                ldsm4(sAh + d, ah[mt][0], ah[mt][1], ah[mt][2], ah[mt][3]);
                ldsm4(sAl + d, al[mt][0], al[mt][1], al[mt][2], al[mt][3]);
            }
#pragma unroll
            for (int np = 0; np < 4; np++) {
                const uint32_t boff =
                    2u * ((uint32_t)((brow + np * 16) * TSTR) + ks * 16 + bcol);
                uint32_t bh[4], bl[4];
                ldsm4(sWh + boff, bh[0], bh[1], bh[2], bh[3]);
                ldsm4(sWl + boff, bl[0], bl[1], bl[2], bl[3]);
#pragma unroll
                for (int mt = 0; mt < 2; mt++) {
#pragma unroll
                    for (int sub = 0; sub < 2; sub++) {
                        float* c = acc[mt][np * 2 + sub];
                        mma16816(c, ah[mt][0], ah[mt][1], ah[mt][2], ah[mt][3],
                                 bh[sub * 2], bh[sub * 2 + 1]);
                        mma16816(c, ah[mt][0], ah[mt][1], ah[mt][2], ah[mt][3],
                                 bl[sub * 2], bl[sub * 2 + 1]);
                        mma16816(c, al[mt][0], al[mt][1], al[mt][2], al[mt][3],
                                 bh[sub * 2], bh[sub * 2 + 1]);
                    }
                }
            }
        }
    }

    /* epilogue */
    const int grp = lane >> 2;
    const int qid = lane & 3;
#pragma unroll
    for (int mt = 0; mt < 2; mt++) {
#pragma unroll
        for (int nt = 0; nt < 8; nt++) {
            const float* c = acc[mt][nt];
            int row = m0 + wm * 32 + mt * 16 + grp;
            int col = j0 + wn * 64 + nt * 8 + qid * 2;
#pragma unroll
            for (int half = 0; half < 2; half++) {
                int m = row + half * 8;
                float vx = c[half * 2], vy = c[half * 2 + 1];
                if (MODE == 0) {
                    int s  = col >> 10;
                    int rr = col & 1023;
                    int h  = rr >> 6;
                    int dh = rr & 63;
                    int b  = m >> 11;
                    int n  = m & 2047;
                    size_t idx = (((size_t)(b * H_ + h) * N_ + n) * DH_ + dh);
                    float sc = (s == 0) ? SCALE_ : 1.f;
                    uint32_t hi, lo;
                    split2(vx * sc, vy * sc, hi, lo);
                    __nv_bfloat16* bhp = (s == 0) ? g_qh : (s == 1) ? g_kh : g_vh;
                    __nv_bfloat16* blp = (s == 0) ? g_ql : (s == 1) ? g_kl : g_vl;
                    *reinterpret_cast<uint32_t*>(bhp + idx) = hi;
                    *reinterpret_cast<uint32_t*>(blp + idx) = lo;
                } else {
                    *reinterpret_cast<float2*>(C + (size_t)m * Nout + col) =
                        make_float2(vx, vy);
                }
            }
        }
    }
}

/* ------------------------------------------------------------------ */
/* Flash-attention on HMMA, inputs pre-split bf16 hi/lo.               */
/* CTA = 128 q-rows of one (b,h); 8 warps x 16 rows; kv tiles of 64.   */
/* ------------------------------------------------------------------ */
#define ASTR 72
#define SM_QH 0
#define SM_QL (128 * ASTR)
#define SM_KH (2 * 128 * ASTR)
#define SM_KL (SM_KH + 64 * ASTR)
#define SM_VH (SM_KL + 64 * ASTR)
#define SM_VL (SM_VH + 64 * ASTR)
#define ATT_SMEM_ELEMS (SM_VL + 64 * ASTR)   /* 36864 bf16 = 73728 B */

__global__ void __launch_bounds__(256)
attn_mma()
{
    extern __shared__ __nv_bfloat16 sbuf[];
    __nv_bfloat16* QH = sbuf + SM_QH;
    __nv_bfloat16* QL = sbuf + SM_QL;
    __nv_bfloat16* KH = sbuf + SM_KH;
    __nv_bfloat16* KL = sbuf + SM_KL;
    __nv_bfloat16* VH = sbuf + SM_VH;
    __nv_bfloat16* VL = sbuf + SM_VL;

    const int qt = (N_ / 128 - 1) - (blockIdx.x >> 5);  /* heavy tiles first */
    const int bh = blockIdx.x & 31;
    const int b  = bh >> 4;
    const int h  = bh & 15;

    const int tid  = threadIdx.x;
    const int lane = tid & 31;
    const int w    = tid >> 5;

    const __nv_bfloat16* Qbh = g_qh + (size_t)bh * N_ * DH_;
    const __nv_bfloat16* Qbl = g_ql + (size_t)bh * N_ * DH_;
    const __nv_bfloat16* Kbh = g_kh + (size_t)bh * N_ * DH_;
    const __nv_bfloat16* Kbl = g_kl + (size_t)bh * N_ * DH_;
    const __nv_bfloat16* Vbh = g_vh + (size_t)bh * N_ * DH_;
    const __nv_bfloat16* Vbl = g_vl + (size_t)bh * N_ * DH_;

    /* ---- load Q tile (pre-scaled, pre-split) ---- */
#pragma unroll
    for (int it = 0; it < 4; it++) {
        int idx = tid + it * 256;            /* 0..1023: 128 rows x 8 */
        int r   = idx >> 3;
        int c8  = (idx & 7) * 8;
        size_t g = (size_t)(qt * 128 + r) * DH_ + c8;
        *reinterpret_cast<uint4*>(QH + r * ASTR + c8) =
            *reinterpret_cast<const uint4*>(Qbh + g);
        *reinterpret_cast<uint4*>(QL + r * ASTR + c8) =
            *reinterpret_cast<const uint4*>(Qbl + g);
    }
    __syncthreads();

    const uint32_t sQH = smem_u32(QH);
    const uint32_t sQL = smem_u32(QL);
    const uint32_t sKH = smem_u32(KH);
    const uint32_t sKL = smem_u32(KL);
    const uint32_t sVH = smem_u32(VH);
    const uint32_t sVL = smem_u32(VL);

    /* ---- Q fragments into registers ---- */
    uint32_t qh[4][4], ql[4][4];
    {
        const uint32_t a0 =
            2u * ((uint32_t)((w * 16 + (lane & 15)) * ASTR) + ((lane >> 4) << 3));
#pragma unroll
        for (int ks = 0; ks < 4; ks++) {
            ldsm4(sQH + a0 + 2u * (ks * 16), qh[ks][0], qh[ks][1], qh[ks][2], qh[ks][3]);
            ldsm4(sQL + a0 + 2u * (ks * 16), ql[ks][0], ql[ks][1], ql[ks][2], ql[ks][3]);
        }
    }

    const uint32_t bpat = 2u * ((uint32_t)(((lane & 7) | ((lane & 16) >> 1)) * ASTR)
                                + (lane & 8));

    float o[8][4];
#pragma unroll
    for (int i = 0; i < 8; i++)
#pragma unroll
        for (int c = 0; c < 4; c++) o[i][c] = 0.f;
    float mrow0 = -INFINITY, mrow1 = -INFINITY;
    float lrow0 = 0.f, lrow1 = 0.f;

    const int qglo   = qt * 128 + w * 16;
    const int ntiles = 2 * qt + 2;

    for (int jt = 0; jt < ntiles; jt++) {
        __syncthreads();
        /* ---- load K tile (raw bf16 copies) ---- */
#pragma unroll
        for (int it = 0; it < 2; it++) {
            int idx = tid + it * 256;         /* 0..511: 64 rows x 8 */
            int r   = idx >> 3;
            int c8  = (idx & 7) * 8;
            size_t g = (size_t)(jt * 64 + r) * DH_ + c8;
            *reinterpret_cast<uint4*>(KH + r * ASTR + c8) =
                *reinterpret_cast<const uint4*>(Kbh + g);
            *reinterpret_cast<uint4*>(KL + r * ASTR + c8) =
                *reinterpret_cast<const uint4*>(Kbl + g);
        }
        /* ---- load V tile transposed ---- */
#pragma unroll
        for (int it = 0; it < 2; it++) {
            int idx = tid + it * 256;
            int j   = idx >> 3;
            int d8  = (idx & 7) * 8;
            size_t g = (size_t)(jt * 64 + j) * DH_ + d8;
            uint4 wh = *reinterpret_cast<const uint4*>(Vbh + g);
            uint4 wl = *reinterpret_cast<const uint4*>(Vbl + g);
            const __nv_bfloat16* ph = reinterpret_cast<const __nv_bfloat16*>(&wh);
            const __nv_bfloat16* pl = reinterpret_cast<const __nv_bfloat16*>(&wl);
#pragma unroll
            for (int e = 0; e < 8; e++) {
                VH[(d8 + e) * ASTR + j] = ph[e];
                VL[(d8 + e) * ASTR + j] = pl[e];
            }
        }
        __syncthreads();

        if (jt * 64 > qglo + 15) continue;

        /* ---- S = Q K^T ---- */
        float s[8][4];
#pragma unroll
        for (int i = 0; i < 8; i++)
#pragma unroll
            for (int c = 0; c < 4; c++) s[i][c] = 0.f;

#pragma unroll
        for (int ks = 0; ks < 4; ks++) {
#pragma unroll
            for (int np = 0; np < 4; np++) {
                const uint32_t boff = bpat + 2u * (np * 16 * ASTR + ks * 16);
                uint32_t bh4[4], bl4[4];
                ldsm4(sKH + boff, bh4[0], bh4[1], bh4[2], bh4[3]);
                ldsm4(sKL + boff, bl4[0], bl4[1], bl4[2], bl4[3]);
#pragma unroll
                for (int sub = 0; sub < 2; sub++) {
                    float* c = s[np * 2 + sub];
                    mma16816(c, qh[ks][0], qh[ks][1], qh[ks][2], qh[ks][3],
                             bh4[sub * 2], bh4[sub * 2 + 1]);
                    mma16816(c, qh[ks][0], qh[ks][1], qh[ks][2], qh[ks][3],
                             bl4[sub * 2], bl4[sub * 2 + 1]);
                    mma16816(c, ql[ks][0], ql[ks][1], ql[ks][2], ql[ks][3],
                             bh4[sub * 2], bh4[sub * 2 + 1]);
                }
            }
        }

        /* ---- causal mask ---- */
        const int r0 = qglo + (lane >> 2);
        const int r1 = r0 + 8;
        if (jt * 64 + 63 > qglo) {
            const int colb = jt * 64 + (lane & 3) * 2;
#pragma unroll
            for (int nt = 0; nt < 8; nt++) {
                int c0 = colb + nt * 8;
                if (c0 > r0)     s[nt][0] = -INFINITY;
                if (c0 + 1 > r0) s[nt][1] = -INFINITY;
                if (c0 > r1)     s[nt][2] = -INFINITY;
                if (c0 + 1 > r1) s[nt][3] = -INFINITY;
            }
        }

        /* ---- online softmax ---- */
        float mt0 = s[0][0], mt1 = s[0][2];
#pragma unroll
        for (int nt = 0; nt < 8; nt++) {
            mt0 = fmaxf(mt0, fmaxf(s[nt][0], s[nt][1]));
            mt1 = fmaxf(mt1, fmaxf(s[nt][2], s[nt][3]));
        }
        mt0 = fmaxf(mt0, __shfl_xor_sync(0xffffffffu, mt0, 1));
        mt0 = fmaxf(mt0, __shfl_xor_sync(0xffffffffu, mt0, 2));
        mt1 = fmaxf(mt1, __shfl_xor_sync(0xffffffffu, mt1, 1));
        mt1 = fmaxf(mt1, __shfl_xor_sync(0xffffffffu, mt1, 2));

        const float mn0 = fmaxf(mrow0, mt0);
        const float mn1 = fmaxf(mrow1, mt1);
        const float al0 = __expf(mrow0 - mn0);
        const float al1 = __expf(mrow1 - mn1);

        float ps0 = 0.f, ps1 = 0.f;
#pragma unroll
        for (int nt = 0; nt < 8; nt++) {
            s[nt][0] = __expf(s[nt][0] - mn0);
            s[nt][1] = __expf(s[nt][1] - mn0);
            s[nt][2] = __expf(s[nt][2] - mn1);
            s[nt][3] = __expf(s[nt][3] - mn1);
            ps0 += s[nt][0] + s[nt][1];
            ps1 += s[nt][2] + s[nt][3];
        }
        ps0 += __shfl_xor_sync(0xffffffffu, ps0, 1);
        ps0 += __shfl_xor_sync(0xffffffffu, ps0, 2);
        ps1 += __shfl_xor_sync(0xffffffffu, ps1, 1);
        ps1 += __shfl_xor_sync(0xffffffffu, ps1, 2);

        lrow0 = lrow0 * al0 + ps0;
        lrow1 = lrow1 * al1 + ps1;
#pragma unroll
        for (int nt = 0; nt < 8; nt++) {
            o[nt][0] *= al0; o[nt][1] *= al0;
            o[nt][2] *= al1; o[nt][3] *= al1;
        }
        mrow0 = mn0;
        mrow1 = mn1;

        /* ---- O += P V ---- */
#pragma unroll
        for (int ks = 0; ks < 4; ks++) {
            uint32_t ph[4], pl[4];
            split2(s[2 * ks][0],     s[2 * ks][1],     ph[0], pl[0]);
            split2(s[2 * ks][2],     s[2 * ks][3],     ph[1], pl[1]);
            split2(s[2 * ks + 1][0], s[2 * ks + 1][1], ph[2], pl[2]);
            split2(s[2 * ks + 1][2], s[2 * ks + 1][3], ph[3], pl[3]);
#pragma unroll
            for (int np = 0; np < 4; np++) {
                const uint32_t boff = bpat + 2u * (np * 16 * ASTR + ks * 16);
                uint32_t bh4[4], bl4[4];
                ldsm4(sVH + boff, bh4[0], bh4[1], bh4[2], bh4[3]);
                ldsm4(sVL + boff, bl4[0], bl4[1], bl4[2], bl4[3]);
#pragma unroll
                for (int sub = 0; sub < 2; sub++) {
                    float* c = o[np * 2 + sub];
                    mma16816(c, ph[0], ph[1], ph[2], ph[3],
                             bh4[sub * 2], bh4[sub * 2 + 1]);
                    mma16816(c, ph[0], ph[1], ph[2], ph[3],
                             bl4[sub * 2], bl4[sub * 2 + 1]);
                    mma16816(c, pl[0], pl[1], pl[2], pl[3],
                             bh4[sub * 2], bh4[sub * 2 + 1]);
                }
            }
        }
    }

    /* ---- epilogue: normalize, split, write ao hi/lo ---- */
    const float i0 = 1.f / lrow0;
    const float i1 = 1.f / lrow1;
    const int r0 = qt * 128 + w * 16 + (lane >> 2);
    const size_t base0 = ((size_t)b * N_ + r0) * D_ + h * DH_ + (lane & 3) * 2;
    const size_t base1 = base0 + 8 * D_;
#pragma unroll
    for (int nt = 0; nt < 8; nt++) {
        uint32_t hi, lo;
        split2(o[nt][0] * i0, o[nt][1] * i0, hi, lo);
        *reinterpret_cast<uint32_t*>(g_aoh + base0 + nt * 8) = hi;
        *reinterpret_cast<uint32_t*>(g_aol + base0 + nt * 8) = lo;
        split2(o[nt][2] * i1, o[nt][3] * i1, hi, lo);
        *reinterpret_cast<uint32_t*>(g_aoh + base1 + nt * 8) = hi;
        *reinterpret_cast<uint32_t*>(g_aol + base1 + nt * 8) = lo;
    }
}

/* ------------------------------------------------------------------ */
extern "C" void kernel_launch(void* const* d_in, const int* in_sizes, int n_in,
                              void* d_out, int out_size)
{
    const float* x    = (const float*)d_in[0];
    /* d_in[1] = mask (static causal structure, unused) */
    const float* Wqkv = (const float*)d_in[2];
    const float* Wout = (const float*)d_in[3];
    float* out = (float*)d_out;

    __nv_bfloat16 *xh, *xl, *wqh, *wql, *woh, *wol, *aoh, *aol;
    cudaGetSymbolAddress((void**)&xh,  g_xh);
    cudaGetSymbolAddress((void**)&xl,  g_xl);
    cudaGetSymbolAddress((void**)&wqh, g_wqh);
    cudaGetSymbolAddress((void**)&wql, g_wql);
    cudaGetSymbolAddress((void**)&woh, g_woh);
    cudaGetSymbolAddress((void**)&wol, g_wol);
    cudaGetSymbolAddress((void**)&aoh, g_aoh);
    cudaGetSymbolAddress((void**)&aol, g_aol);

    /* 0. split inputs to bf16 hi/lo */
    split_fp32<<<1024, 256>>>(x,    xh,  xl,  4096 * 1024 / 4);
    split_fp32<<<1024, 256>>>(Wqkv, wqh, wql, 3072 * 1024 / 4);
    split_fp32<<<512,  256>>>(Wout, woh, wol, 1024 * 1024 / 4);

    cudaFuncSetAttribute(gemm_bf16<0>,
                         cudaFuncAttributeMaxDynamicSharedMemorySize, GEMM_SMEM);
    cudaFuncSetAttribute(gemm_bf16<1>,
                         cudaFuncAttributeMaxDynamicSharedMemorySize, GEMM_SMEM);

    /* 1. QKV projection -> q/k/v hi/lo (q pre-scaled) */
    gemm_bf16<0><<<dim3(3072 / 128, 4096 / 128), 256, GEMM_SMEM>>>(
        xh, xl, wqh, wql, nullptr, D_, 3 * D_);

    /* 2. causal flash attention -> ao hi/lo */
    const int ATT_SMEM = ATT_SMEM_ELEMS * (int)sizeof(__nv_bfloat16);
    cudaFuncSetAttribute(attn_mma,
                         cudaFuncAttributeMaxDynamicSharedMemorySize, ATT_SMEM);
    attn_mma<<<dim3((N_ / 128) * 32), 256, ATT_SMEM>>>();

    /* 3. output projection -> d_out (fp32) */
    gemm_bf16<1><<<dim3(1024 / 128, 4096 / 128), 256, GEMM_SMEM>>>(
        aoh, aol, woh, wol, out, D_, D_);
}

// round 6
// speedup vs baseline: 1.5228x; 1.5228x over previous
#include <cuda_runtime.h>
#include <cuda_bf16.h>
#include <math.h>
#include <stdint.h>

#define B_ 2
#define N_ 2048
#define D_ 1024
#define H_ 16
#define DH_ 64
#define SCALE_ 0.125f   /* 64^-0.5, exact power of two */

/* ------------------------------------------------------------------ */
/* device scratch: everything bf16 hi/lo pairs                         */
/* ------------------------------------------------------------------ */
__device__ __nv_bfloat16 g_xh [4096 * 1024], g_xl [4096 * 1024];
__device__ __nv_bfloat16 g_wqh[3072 * 1024], g_wql[3072 * 1024];
__device__ __nv_bfloat16 g_woh[1024 * 1024], g_wol[1024 * 1024];
__device__ __nv_bfloat16 g_qh [B_*H_*N_*DH_], g_ql [B_*H_*N_*DH_];
__device__ __nv_bfloat16 g_kh [B_*H_*N_*DH_], g_kl [B_*H_*N_*DH_];
__device__ __nv_bfloat16 g_vh [B_*H_*N_*DH_], g_vl [B_*H_*N_*DH_];
__device__ __nv_bfloat16 g_aoh[B_*N_*D_],     g_aol[B_*N_*D_];

/* ------------------------------------------------------------------ */
/* helpers                                                             */
/* ------------------------------------------------------------------ */
__device__ __forceinline__ uint32_t smem_u32(const void* p) {
    uint32_t a;
    asm("{ .reg .u64 t; cvta.to.shared.u64 t, %1; cvt.u32.u64 %0, t; }"
        : "=r"(a) : "l"(p));
    return a;
}

__device__ __forceinline__ void ldsm4(uint32_t addr, uint32_t& r0, uint32_t& r1,
                                      uint32_t& r2, uint32_t& r3) {
    asm volatile("ldmatrix.sync.aligned.m8n8.x4.shared.b16 {%0,%1,%2,%3}, [%4];"
                 : "=r"(r0), "=r"(r1), "=r"(r2), "=r"(r3) : "r"(addr));
}

__device__ __forceinline__ void mma16816(float* c,
                                         uint32_t a0, uint32_t a1, uint32_t a2, uint32_t a3,
                                         uint32_t b0, uint32_t b1) {
    asm volatile(
        "mma.sync.aligned.m16n8k16.row.col.f32.bf16.bf16.f32 "
        "{%0,%1,%2,%3}, {%4,%5,%6,%7}, {%8,%9}, {%0,%1,%2,%3};"
        : "+f"(c[0]), "+f"(c[1]), "+f"(c[2]), "+f"(c[3])
        : "r"(a0), "r"(a1), "r"(a2), "r"(a3), "r"(b0), "r"(b1));
}

__device__ __forceinline__ void split2(float x, float y, uint32_t& hi, uint32_t& lo) {
    __nv_bfloat162 h = __floats2bfloat162_rn(x, y);
    float rx = x - __bfloat162float(h.x);
    float ry = y - __bfloat162float(h.y);
    __nv_bfloat162 l = __floats2bfloat162_rn(rx, ry);
    hi = *reinterpret_cast<uint32_t*>(&h);
    lo = *reinterpret_cast<uint32_t*>(&l);
}

/* ------------------------------------------------------------------ */
/* split kernel: fp32 -> bf16 hi/lo pair                               */
/* ------------------------------------------------------------------ */
__global__ void __launch_bounds__(256)
split_fp32(const float* __restrict__ src, __nv_bfloat16* __restrict__ h,
           __nv_bfloat16* __restrict__ l, int n4)
{
    int i      = blockIdx.x * blockDim.x + threadIdx.x;
    int stride = gridDim.x * blockDim.x;
    for (; i < n4; i += stride) {
        float4 v = reinterpret_cast<const float4*>(src)[i];
        uint32_t h0, l0, h1, l1;
        split2(v.x, v.y, h0, l0);
        split2(v.z, v.w, h1, l1);
        reinterpret_cast<uint2*>(h)[i] = make_uint2(h0, h1);
        reinterpret_cast<uint2*>(l)[i] = make_uint2(l0, l1);
    }
}

/* ------------------------------------------------------------------ */
/* HMMA GEMM on pre-split bf16: C = A * W^T.                           */
/* tile 128x128, BK=32, 256 thr (8 warps 4x2).                         */
/* Register-staged double buffer: LDG chunk kc+1 during MMA of kc.     */
/* MODE 0: epilogue -> q/k/v hi/lo (q scaled). MODE 1: fp32 C store.   */
/* ------------------------------------------------------------------ */
#define TSTR 40
#define TILE_E (128 * TSTR)                    /* bf16 elems per array */
#define GEMM_SMEM (2 * 4 * TILE_E * 2)         /* 81920 B dynamic      */

template <int MODE>
__global__ void __launch_bounds__(256)
gemm_bf16(const __nv_bfloat16* __restrict__ Ah, const __nv_bfloat16* __restrict__ Al,
          const __nv_bfloat16* __restrict__ Wh, const __nv_bfloat16* __restrict__ Wl,
          float* __restrict__ C, int K, int Nout)
{
    extern __shared__ __nv_bfloat16 smem[];
    const uint32_t sb = smem_u32(smem);

    const int tid  = threadIdx.x;
    const int lane = tid & 31;
    const int wid  = tid >> 5;
    const int wm   = wid & 3;
    const int wn   = wid >> 2;

    const int m0 = blockIdx.y * 128;
    const int j0 = blockIdx.x * 128;

    /* per-thread load slots: idx = tid + i*256, row = idx>>2, q = idx&3 */
    const int row0 = tid >> 2;
    const int row1 = (tid + 256) >> 2;
    const int q0   = tid & 3;
    const size_t gA0 = (size_t)(m0 + row0) * K + q0 * 8;
    const size_t gA1 = (size_t)(m0 + row1) * K + q0 * 8;
    const size_t gW0 = (size_t)(j0 + row0) * K + q0 * 8;
    const size_t gW1 = (size_t)(j0 + row1) * K + q0 * 8;
    const uint32_t so0 = (uint32_t)(row0 * TSTR + q0 * 8);
    const uint32_t so1 = (uint32_t)(row1 * TSTR + q0 * 8);

    uint4 rAh[2], rAl[2], rWh[2], rWl[2];

#define LOAD_REGS(kc)                                                         \
    do {                                                                      \
        const int koff = (kc) * 32;                                          \
        rAh[0] = *reinterpret_cast<const uint4*>(Ah + gA0 + koff);           \
        rAh[1] = *reinterpret_cast<const uint4*>(Ah + gA1 + koff);           \
        rAl[0] = *reinterpret_cast<const uint4*>(Al + gA0 + koff);           \
        rAl[1] = *reinterpret_cast<const uint4*>(Al + gA1 + koff);           \
        rWh[0] = *reinterpret_cast<const uint4*>(Wh + gW0 + koff);           \
        rWh[1] = *reinterpret_cast<const uint4*>(Wh + gW1 + koff);           \
        rWl[0] = *reinterpret_cast<const uint4*>(Wl + gW0 + koff);           \
        rWl[1] = *reinterpret_cast<const uint4*>(Wl + gW1 + koff);           \
    } while (0)

#define STS_REGS(stage)                                                       \
    do {                                                                      \
        __nv_bfloat16* base = smem + (stage) * 4 * TILE_E;                   \
        *reinterpret_cast<uint4*>(base + 0 * TILE_E + so0) = rAh[0];         \
        *reinterpret_cast<uint4*>(base + 0 * TILE_E + so1) = rAh[1];         \
        *reinterpret_cast<uint4*>(base + 1 * TILE_E + so0) = rAl[0];         \
        *reinterpret_cast<uint4*>(base + 1 * TILE_E + so1) = rAl[1];         \
        *reinterpret_cast<uint4*>(base + 2 * TILE_E + so0) = rWh[0];         \
        *reinterpret_cast<uint4*>(base + 2 * TILE_E + so1) = rWh[1];         \
        *reinterpret_cast<uint4*>(base + 3 * TILE_E + so0) = rWl[0];         \
        *reinterpret_cast<uint4*>(base + 3 * TILE_E + so1) = rWl[1];         \
    } while (0)

    const int arow = wm * 32 + (lane & 15);
    const int acol = (lane >> 4) << 3;
    const int brow = wn * 64 + ((lane & 7) | ((lane & 16) >> 1));
    const int bcol = lane & 8;

    float acc[2][8][4];
#pragma unroll
    for (int i = 0; i < 2; i++)
#pragma unroll
        for (int j = 0; j < 8; j++)
#pragma unroll
            for (int c = 0; c < 4; c++) acc[i][j][c] = 0.f;

    const int nchunk = K >> 5;

    /* prologue: chunk 0 into stage 0 */
    LOAD_REGS(0);
    STS_REGS(0);
    __syncthreads();

    for (int kc = 0; kc < nchunk; kc++) {
        /* issue next chunk's LDGs; latency covered by MMA phase below */
        if (kc + 1 < nchunk) LOAD_REGS(kc + 1);

        const uint32_t st  = sb + (uint32_t)(kc & 1) * 4 * TILE_E * 2;
        const uint32_t sAh = st;
        const uint32_t sAl = st + 1 * TILE_E * 2;
        const uint32_t sWh = st + 2 * TILE_E * 2;
        const uint32_t sWl = st + 3 * TILE_E * 2;

#pragma unroll
        for (int ks = 0; ks < 2; ks++) {
            const uint32_t aoff = 2u * ((uint32_t)(arow * TSTR) + ks * 16 + acol);
            uint32_t ah[2][4], al[2][4];
#pragma unroll
            for (int mt = 0; mt < 2; mt++) {
                uint32_t d = aoff + 2u * (mt * 16 * TSTR);
                ldsm4(sAh + d, ah[mt][0], ah[mt][1], ah[mt][2], ah[mt][3]);
                ldsm4(sAl + d, al[mt][0], al[mt][1], al[mt][2], al[mt][3]);
            }
#pragma unroll
            for (int np = 0; np < 4; np++) {
                const uint32_t boff =
                    2u * ((uint32_t)((brow + np * 16) * TSTR) + ks * 16 + bcol);
                uint32_t bh[4], bl[4];
                ldsm4(sWh + boff, bh[0], bh[1], bh[2], bh[3]);
                ldsm4(sWl + boff, bl[0], bl[1], bl[2], bl[3]);
#pragma unroll
                for (int mt = 0; mt < 2; mt++) {
#pragma unroll
                    for (int sub = 0; sub < 2; sub++) {
                        float* c = acc[mt][np * 2 + sub];
                        mma16816(c, ah[mt][0], ah[mt][1], ah[mt][2], ah[mt][3],
                                 bh[sub * 2], bh[sub * 2 + 1]);
                        mma16816(c, ah[mt][0], ah[mt][1], ah[mt][2], ah[mt][3],
                                 bl[sub * 2], bl[sub * 2 + 1]);
                        mma16816(c, al[mt][0], al[mt][1], al[mt][2], al[mt][3],
                                 bh[sub * 2], bh[sub * 2 + 1]);
                    }
                }
            }
        }

        /* store next chunk into the other stage; one sync per chunk */
        if (kc + 1 < nchunk) {
            STS_REGS((kc + 1) & 1);
            __syncthreads();
        }
    }

    /* epilogue */
    const int grp = lane >> 2;
    const int qid = lane & 3;
#pragma unroll
    for (int mt = 0; mt < 2; mt++) {
#pragma unroll
        for (int nt = 0; nt < 8; nt++) {
            const float* c = acc[mt][nt];
            int row = m0 + wm * 32 + mt * 16 + grp;
            int col = j0 + wn * 64 + nt * 8 + qid * 2;
#pragma unroll
            for (int half = 0; half < 2; half++) {
                int m = row + half * 8;
                float vx = c[half * 2], vy = c[half * 2 + 1];
                if (MODE == 0) {
                    int s  = col >> 10;
                    int rr = col & 1023;
                    int h  = rr >> 6;
                    int dh = rr & 63;
                    int b  = m >> 11;
                    int n  = m & 2047;
                    size_t idx = (((size_t)(b * H_ + h) * N_ + n) * DH_ + dh);
                    float sc = (s == 0) ? SCALE_ : 1.f;
                    uint32_t hi, lo;
                    split2(vx * sc, vy * sc, hi, lo);
                    __nv_bfloat16* bhp = (s == 0) ? g_qh : (s == 1) ? g_kh : g_vh;
                    __nv_bfloat16* blp = (s == 0) ? g_ql : (s == 1) ? g_kl : g_vl;
                    *reinterpret_cast<uint32_t*>(bhp + idx) = hi;
                    *reinterpret_cast<uint32_t*>(blp + idx) = lo;
                } else {
                    *reinterpret_cast<float2*>(C + (size_t)m * Nout + col) =
                        make_float2(vx, vy);
                }
            }
        }
    }
}

/* ------------------------------------------------------------------ */
/* Flash-attention on HMMA, inputs pre-split bf16 hi/lo (R5 version).  */
/* ------------------------------------------------------------------ */
#define ASTR 72
#define SM_QH 0
#define SM_QL (128 * ASTR)
#define SM_KH (2 * 128 * ASTR)
#define SM_KL (SM_KH + 64 * ASTR)
#define SM_VH (SM_KL + 64 * ASTR)
#define SM_VL (SM_VH + 64 * ASTR)
#define ATT_SMEM_ELEMS (SM_VL + 64 * ASTR)   /* 36864 bf16 = 73728 B */

__global__ void __launch_bounds__(256)
attn_mma()
{
    extern __shared__ __nv_bfloat16 sbuf[];
    __nv_bfloat16* QH = sbuf + SM_QH;
    __nv_bfloat16* QL = sbuf + SM_QL;
    __nv_bfloat16* KH = sbuf + SM_KH;
    __nv_bfloat16* KL = sbuf + SM_KL;
    __nv_bfloat16* VH = sbuf + SM_VH;
    __nv_bfloat16* VL = sbuf + SM_VL;

    const int qt = (N_ / 128 - 1) - (blockIdx.x >> 5);  /* heavy tiles first */
    const int bh = blockIdx.x & 31;
    const int b  = bh >> 4;
    const int h  = bh & 15;

    const int tid  = threadIdx.x;
    const int lane = tid & 31;
    const int w    = tid >> 5;

    const __nv_bfloat16* Qbh = g_qh + (size_t)bh * N_ * DH_;
    const __nv_bfloat16* Qbl = g_ql + (size_t)bh * N_ * DH_;
    const __nv_bfloat16* Kbh = g_kh + (size_t)bh * N_ * DH_;
    const __nv_bfloat16* Kbl = g_kl + (size_t)bh * N_ * DH_;
    const __nv_bfloat16* Vbh = g_vh + (size_t)bh * N_ * DH_;
    const __nv_bfloat16* Vbl = g_vl + (size_t)bh * N_ * DH_;

    /* ---- load Q tile (pre-scaled, pre-split) ---- */
#pragma unroll
    for (int it = 0; it < 4; it++) {
        int idx = tid + it * 256;
        int r   = idx >> 3;
        int c8  = (idx & 7) * 8;
        size_t g = (size_t)(qt * 128 + r) * DH_ + c8;
        *reinterpret_cast<uint4*>(QH + r * ASTR + c8) =
            *reinterpret_cast<const uint4*>(Qbh + g);
        *reinterpret_cast<uint4*>(QL + r * ASTR + c8) =
            *reinterpret_cast<const uint4*>(Qbl + g);
    }
    __syncthreads();

    const uint32_t sQH = smem_u32(QH);
    const uint32_t sQL = smem_u32(QL);
    const uint32_t sKH = smem_u32(KH);
    const uint32_t sKL = smem_u32(KL);
    const uint32_t sVH = smem_u32(VH);
    const uint32_t sVL = smem_u32(VL);

    /* ---- Q fragments into registers ---- */
    uint32_t qh[4][4], ql[4][4];
    {
        const uint32_t a0 =
            2u * ((uint32_t)((w * 16 + (lane & 15)) * ASTR) + ((lane >> 4) << 3));
#pragma unroll
        for (int ks = 0; ks < 4; ks++) {
            ldsm4(sQH + a0 + 2u * (ks * 16), qh[ks][0], qh[ks][1], qh[ks][2], qh[ks][3]);
            ldsm4(sQL + a0 + 2u * (ks * 16), ql[ks][0], ql[ks][1], ql[ks][2], ql[ks][3]);
        }
    }

    const uint32_t bpat = 2u * ((uint32_t)(((lane & 7) | ((lane & 16) >> 1)) * ASTR)
                                + (lane & 8));

    float o[8][4];
#pragma unroll
    for (int i = 0; i < 8; i++)
#pragma unroll
        for (int c = 0; c < 4; c++) o[i][c] = 0.f;
    float mrow0 = -INFINITY, mrow1 = -INFINITY;
    float lrow0 = 0.f, lrow1 = 0.f;

    const int qglo   = qt * 128 + w * 16;
    const int ntiles = 2 * qt + 2;

    for (int jt = 0; jt < ntiles; jt++) {
        __syncthreads();
#pragma unroll
        for (int it = 0; it < 2; it++) {
            int idx = tid + it * 256;
            int r   = idx >> 3;
            int c8  = (idx & 7) * 8;
            size_t g = (size_t)(jt * 64 + r) * DH_ + c8;
            *reinterpret_cast<uint4*>(KH + r * ASTR + c8) =
                *reinterpret_cast<const uint4*>(Kbh + g);
            *reinterpret_cast<uint4*>(KL + r * ASTR + c8) =
                *reinterpret_cast<const uint4*>(Kbl + g);
        }
#pragma unroll
        for (int it = 0; it < 2; it++) {
            int idx = tid + it * 256;
            int j   = idx >> 3;
            int d8  = (idx & 7) * 8;
            size_t g = (size_t)(jt * 64 + j) * DH_ + d8;
            uint4 wh = *reinterpret_cast<const uint4*>(Vbh + g);
            uint4 wl = *reinterpret_cast<const uint4*>(Vbl + g);
            const __nv_bfloat16* ph = reinterpret_cast<const __nv_bfloat16*>(&wh);
            const __nv_bfloat16* pl = reinterpret_cast<const __nv_bfloat16*>(&wl);
#pragma unroll
            for (int e = 0; e < 8; e++) {
                VH[(d8 + e) * ASTR + j] = ph[e];
                VL[(d8 + e) * ASTR + j] = pl[e];
            }
        }
        __syncthreads();

        if (jt * 64 > qglo + 15) continue;

        /* ---- S = Q K^T ---- */
        float s[8][4];
#pragma unroll
        for (int i = 0; i < 8; i++)
#pragma unroll
            for (int c = 0; c < 4; c++) s[i][c] = 0.f;

#pragma unroll
        for (int ks = 0; ks < 4; ks++) {
#pragma unroll
            for (int np = 0; np < 4; np++) {
                const uint32_t boff = bpat + 2u * (np * 16 * ASTR + ks * 16);
                uint32_t bh4[4], bl4[4];
                ldsm4(sKH + boff, bh4[0], bh4[1], bh4[2], bh4[3]);
                ldsm4(sKL + boff, bl4[0], bl4[1], bl4[2], bl4[3]);
#pragma unroll
                for (int sub = 0; sub < 2; sub++) {
                    float* c = s[np * 2 + sub];
                    mma16816(c, qh[ks][0], qh[ks][1], qh[ks][2], qh[ks][3],
                             bh4[sub * 2], bh4[sub * 2 + 1]);
                    mma16816(c, qh[ks][0], qh[ks][1], qh[ks][2], qh[ks][3],
                             bl4[sub * 2], bl4[sub * 2 + 1]);
                    mma16816(c, ql[ks][0], ql[ks][1], ql[ks][2], ql[ks][3],
                             bh4[sub * 2], bh4[sub * 2 + 1]);
                }
            }
        }

        /* ---- causal mask ---- */
        const int r0 = qglo + (lane >> 2);
        const int r1 = r0 + 8;
        if (jt * 64 + 63 > qglo) {
            const int colb = jt * 64 + (lane & 3) * 2;
#pragma unroll
            for (int nt = 0; nt < 8; nt++) {
                int c0 = colb + nt * 8;
                if (c0 > r0)     s[nt][0] = -INFINITY;
                if (c0 + 1 > r0) s[nt][1] = -INFINITY;
                if (c0 > r1)     s[nt][2] = -INFINITY;
                if (c0 + 1 > r1) s[nt][3] = -INFINITY;
            }
        }

        /* ---- online softmax ---- */
        float mt0 = s[0][0], mt1 = s[0][2];
#pragma unroll
        for (int nt = 0; nt < 8; nt++) {
            mt0 = fmaxf(mt0, fmaxf(s[nt][0], s[nt][1]));
            mt1 = fmaxf(mt1, fmaxf(s[nt][2], s[nt][3]));
        }
        mt0 = fmaxf(mt0, __shfl_xor_sync(0xffffffffu, mt0, 1));
        mt0 = fmaxf(mt0, __shfl_xor_sync(0xffffffffu, mt0, 2));
        mt1 = fmaxf(mt1, __shfl_xor_sync(0xffffffffu, mt1, 1));
        mt1 = fmaxf(mt1, __shfl_xor_sync(0xffffffffu, mt1, 2));

        const float mn0 = fmaxf(mrow0, mt0);
        const float mn1 = fmaxf(mrow1, mt1);
        const float al0 = __expf(mrow0 - mn0);
        const float al1 = __expf(mrow1 - mn1);

        float ps0 = 0.f, ps1 = 0.f;
#pragma unroll
        for (int nt = 0; nt < 8; nt++) {
            s[nt][0] = __expf(s[nt][0] - mn0);
            s[nt][1] = __expf(s[nt][1] - mn0);
            s[nt][2] = __expf(s[nt][2] - mn1);
            s[nt][3] = __expf(s[nt][3] - mn1);
            ps0 += s[nt][0] + s[nt][1];
            ps1 += s[nt][2] + s[nt][3];
        }
        ps0 += __shfl_xor_sync(0xffffffffu, ps0, 1);
        ps0 += __shfl_xor_sync(0xffffffffu, ps0, 2);
        ps1 += __shfl_xor_sync(0xffffffffu, ps1, 1);
        ps1 += __shfl_xor_sync(0xffffffffu, ps1, 2);

        lrow0 = lrow0 * al0 + ps0;
        lrow1 = lrow1 * al1 + ps1;
#pragma unroll
        for (int nt = 0; nt < 8; nt++) {
            o[nt][0] *= al0; o[nt][1] *= al0;
            o[nt][2] *= al1; o[nt][3] *= al1;
        }
        mrow0 = mn0;
        mrow1 = mn1;

        /* ---- O += P V ---- */
#pragma unroll
        for (int ks = 0; ks < 4; ks++) {
            uint32_t ph[4], pl[4];
            split2(s[2 * ks][0],     s[2 * ks][1],     ph[0], pl[0]);
            split2(s[2 * ks][2],     s[2 * ks][3],     ph[1], pl[1]);
            split2(s[2 * ks + 1][0], s[2 * ks + 1][1], ph[2], pl[2]);
            split2(s[2 * ks + 1][2], s[2 * ks + 1][3], ph[3], pl[3]);
#pragma unroll
            for (int np = 0; np < 4; np++) {
                const uint32_t boff = bpat + 2u * (np * 16 * ASTR + ks * 16);
                uint32_t bh4[4], bl4[4];
                ldsm4(sVH + boff, bh4[0], bh4[1], bh4[2], bh4[3]);
                ldsm4(sVL + boff, bl4[0], bl4[1], bl4[2], bl4[3]);
#pragma unroll
                for (int sub = 0; sub < 2; sub++) {
                    float* c = o[np * 2 + sub];
                    mma16816(c, ph[0], ph[1], ph[2], ph[3],
                             bh4[sub * 2], bh4[sub * 2 + 1]);
                    mma16816(c, ph[0], ph[1], ph[2], ph[3],
                             bl4[sub * 2], bl4[sub * 2 + 1]);
                    mma16816(c, pl[0], pl[1], pl[2], pl[3],
                             bh4[sub * 2], bh4[sub * 2 + 1]);
                }
            }
        }
    }

    /* ---- epilogue ---- */
    const float i0 = 1.f / lrow0;
    const float i1 = 1.f / lrow1;
    const int r0 = qt * 128 + w * 16 + (lane >> 2);
    const size_t base0 = ((size_t)b * N_ + r0) * D_ + h * DH_ + (lane & 3) * 2;
    const size_t base1 = base0 + 8 * D_;
#pragma unroll
    for (int nt = 0; nt < 8; nt++) {
        uint32_t hi, lo;
        split2(o[nt][0] * i0, o[nt][1] * i0, hi, lo);
        *reinterpret_cast<uint32_t*>(g_aoh + base0 + nt * 8) = hi;
        *reinterpret_cast<uint32_t*>(g_aol + base0 + nt * 8) = lo;
        split2(o[nt][2] * i1, o[nt][3] * i1, hi, lo);
        *reinterpret_cast<uint32_t*>(g_aoh + base1 + nt * 8) = hi;
        *reinterpret_cast<uint32_t*>(g_aol + base1 + nt * 8) = lo;
    }
}

/* ------------------------------------------------------------------ */
extern "C" void kernel_launch(void* const* d_in, const int* in_sizes, int n_in,
                              void* d_out, int out_size)
{
    const float* x    = (const float*)d_in[0];
    /* d_in[1] = mask (static causal structure, unused) */
    const float* Wqkv = (const float*)d_in[2];
    const float* Wout = (const float*)d_in[3];
    float* out = (float*)d_out;

    __nv_bfloat16 *xh, *xl, *wqh, *wql, *woh, *wol, *aoh, *aol;
    cudaGetSymbolAddress((void**)&xh,  g_xh);
    cudaGetSymbolAddress((void**)&xl,  g_xl);
    cudaGetSymbolAddress((void**)&wqh, g_wqh);
    cudaGetSymbolAddress((void**)&wql, g_wql);
    cudaGetSymbolAddress((void**)&woh, g_woh);
    cudaGetSymbolAddress((void**)&wol, g_wol);
    cudaGetSymbolAddress((void**)&aoh, g_aoh);
    cudaGetSymbolAddress((void**)&aol, g_aol);

    /* 0. split inputs to bf16 hi/lo */
    split_fp32<<<1024, 256>>>(x,    xh,  xl,  4096 * 1024 / 4);
    split_fp32<<<1024, 256>>>(Wqkv, wqh, wql, 3072 * 1024 / 4);
    split_fp32<<<512,  256>>>(Wout, woh, wol, 1024 * 1024 / 4);

    cudaFuncSetAttribute(gemm_bf16<0>,
                         cudaFuncAttributeMaxDynamicSharedMemorySize, GEMM_SMEM);
    cudaFuncSetAttribute(gemm_bf16<1>,
                         cudaFuncAttributeMaxDynamicSharedMemorySize, GEMM_SMEM);

    /* 1. QKV projection -> q/k/v hi/lo (q pre-scaled) */
    gemm_bf16<0><<<dim3(3072 / 128, 4096 / 128), 256, GEMM_SMEM>>>(
        xh, xl, wqh, wql, nullptr, D_, 3 * D_);

    /* 2. causal flash attention -> ao hi/lo */
    const int ATT_SMEM = ATT_SMEM_ELEMS * (int)sizeof(__nv_bfloat16);
    cudaFuncSetAttribute(attn_mma,
                         cudaFuncAttributeMaxDynamicSharedMemorySize, ATT_SMEM);
    attn_mma<<<dim3((N_ / 128) * 32), 256, ATT_SMEM>>>();

    /* 3. output projection -> d_out (fp32) */
    gemm_bf16<1><<<dim3(1024 / 128, 4096 / 128), 256, GEMM_SMEM>>>(
        aoh, aol, woh, wol, out, D_, D_);
}

// round 7
// speedup vs baseline: 1.6530x; 1.0855x over previous
#include <cuda_runtime.h>
#include <cuda_bf16.h>
#include <math.h>
#include <stdint.h>

#define B_ 2
#define N_ 2048
#define D_ 1024
#define H_ 16
#define DH_ 64
#define SCALE_ 0.125f   /* 64^-0.5, exact power of two */

/* ------------------------------------------------------------------ */
/* device scratch: everything bf16 hi/lo pairs                         */
/* ------------------------------------------------------------------ */
__device__ __nv_bfloat16 g_xh [4096 * 1024], g_xl [4096 * 1024];
__device__ __nv_bfloat16 g_wqh[3072 * 1024], g_wql[3072 * 1024];
__device__ __nv_bfloat16 g_woh[1024 * 1024], g_wol[1024 * 1024];
__device__ __nv_bfloat16 g_qh [B_*H_*N_*DH_], g_ql [B_*H_*N_*DH_];
__device__ __nv_bfloat16 g_kh [B_*H_*N_*DH_], g_kl [B_*H_*N_*DH_];
__device__ __nv_bfloat16 g_vh [B_*H_*N_*DH_], g_vl [B_*H_*N_*DH_];
__device__ __nv_bfloat16 g_aoh[B_*N_*D_],     g_aol[B_*N_*D_];

/* ------------------------------------------------------------------ */
/* helpers                                                             */
/* ------------------------------------------------------------------ */
__device__ __forceinline__ uint32_t smem_u32(const void* p) {
    uint32_t a;
    asm("{ .reg .u64 t; cvta.to.shared.u64 t, %1; cvt.u32.u64 %0, t; }"
        : "=r"(a) : "l"(p));
    return a;
}

__device__ __forceinline__ void ldsm4(uint32_t addr, uint32_t& r0, uint32_t& r1,
                                      uint32_t& r2, uint32_t& r3) {
    asm volatile("ldmatrix.sync.aligned.m8n8.x4.shared.b16 {%0,%1,%2,%3}, [%4];"
                 : "=r"(r0), "=r"(r1), "=r"(r2), "=r"(r3) : "r"(addr));
}

__device__ __forceinline__ void mma16816(float* c,
                                         uint32_t a0, uint32_t a1, uint32_t a2, uint32_t a3,
                                         uint32_t b0, uint32_t b1) {
    asm volatile(
        "mma.sync.aligned.m16n8k16.row.col.f32.bf16.bf16.f32 "
        "{%0,%1,%2,%3}, {%4,%5,%6,%7}, {%8,%9}, {%0,%1,%2,%3};"
        : "+f"(c[0]), "+f"(c[1]), "+f"(c[2]), "+f"(c[3])
        : "r"(a0), "r"(a1), "r"(a2), "r"(a3), "r"(b0), "r"(b1));
}

__device__ __forceinline__ void split2(float x, float y, uint32_t& hi, uint32_t& lo) {
    __nv_bfloat162 h = __floats2bfloat162_rn(x, y);
    float rx = x - __bfloat162float(h.x);
    float ry = y - __bfloat162float(h.y);
    __nv_bfloat162 l = __floats2bfloat162_rn(rx, ry);
    hi = *reinterpret_cast<uint32_t*>(&h);
    lo = *reinterpret_cast<uint32_t*>(&l);
}

/* ------------------------------------------------------------------ */
/* split kernel: fp32 -> bf16 hi/lo pair                               */
/* ------------------------------------------------------------------ */
__global__ void __launch_bounds__(256)
split_fp32(const float* __restrict__ src, __nv_bfloat16* __restrict__ h,
           __nv_bfloat16* __restrict__ l, int n4)
{
    int i      = blockIdx.x * blockDim.x + threadIdx.x;
    int stride = gridDim.x * blockDim.x;
    for (; i < n4; i += stride) {
        float4 v = reinterpret_cast<const float4*>(src)[i];
        uint32_t h0, l0, h1, l1;
        split2(v.x, v.y, h0, l0);
        split2(v.z, v.w, h1, l1);
        reinterpret_cast<uint2*>(h)[i] = make_uint2(h0, h1);
        reinterpret_cast<uint2*>(l)[i] = make_uint2(l0, l1);
    }
}

/* ------------------------------------------------------------------ */
/* HMMA GEMM on pre-split bf16: C = A * W^T.                           */
/* tile 128x128, BK=32, 256 thr (8 warps 4x2), 2 CTAs/SM.              */
/* smem double buffer; next-chunk LDG+STS issued before MMA phase.     */
/* MODE 0: epilogue -> q/k/v hi/lo (q scaled). MODE 1: fp32 C store.   */
/* ------------------------------------------------------------------ */
#define TSTR 40
#define TILE_E (128 * TSTR)                    /* bf16 elems per array */
#define GEMM_SMEM (2 * 4 * TILE_E * 2)         /* 81920 B dynamic      */

template <int MODE>
__global__ void __launch_bounds__(256, 2)
gemm_bf16(const __nv_bfloat16* __restrict__ Ah, const __nv_bfloat16* __restrict__ Al,
          const __nv_bfloat16* __restrict__ Wh, const __nv_bfloat16* __restrict__ Wl,
          float* __restrict__ C, int K, int Nout)
{
    extern __shared__ __nv_bfloat16 smem[];
    const uint32_t sb = smem_u32(smem);

    const int tid  = threadIdx.x;
    const int lane = tid & 31;
    const int wid  = tid >> 5;
    const int wm   = wid & 3;
    const int wn   = wid >> 2;

    const int m0 = blockIdx.y * 128;
    const int j0 = blockIdx.x * 128;

    /* per-thread load slots: idx = tid + i*256, row = idx>>2, q = idx&3 */
    const int row0 = tid >> 2;
    const int row1 = (tid + 256) >> 2;
    const int q0   = tid & 3;
    const size_t gA0 = (size_t)(m0 + row0) * K + q0 * 8;
    const size_t gA1 = (size_t)(m0 + row1) * K + q0 * 8;
    const size_t gW0 = (size_t)(j0 + row0) * K + q0 * 8;
    const size_t gW1 = (size_t)(j0 + row1) * K + q0 * 8;
    const uint32_t so0 = (uint32_t)(row0 * TSTR + q0 * 8);
    const uint32_t so1 = (uint32_t)(row1 * TSTR + q0 * 8);

#define LOAD_CHUNK(kc, stage)                                                 \
    do {                                                                      \
        const int koff = (kc) * 32;                                          \
        __nv_bfloat16* base = smem + (stage) * 4 * TILE_E;                   \
        *reinterpret_cast<uint4*>(base + 0 * TILE_E + so0) =                 \
            *reinterpret_cast<const uint4*>(Ah + gA0 + koff);                \
        *reinterpret_cast<uint4*>(base + 0 * TILE_E + so1) =                 \
            *reinterpret_cast<const uint4*>(Ah + gA1 + koff);                \
        *reinterpret_cast<uint4*>(base + 1 * TILE_E + so0) =                 \
            *reinterpret_cast<const uint4*>(Al + gA0 + koff);                \
        *reinterpret_cast<uint4*>(base + 1 * TILE_E + so1) =                 \
            *reinterpret_cast<const uint4*>(Al + gA1 + koff);                \
        *reinterpret_cast<uint4*>(base + 2 * TILE_E + so0) =                 \
            *reinterpret_cast<const uint4*>(Wh + gW0 + koff);                \
        *reinterpret_cast<uint4*>(base + 2 * TILE_E + so1) =                 \
            *reinterpret_cast<const uint4*>(Wh + gW1 + koff);                \
        *reinterpret_cast<uint4*>(base + 3 * TILE_E + so0) =                 \
            *reinterpret_cast<const uint4*>(Wl + gW0 + koff);                \
        *reinterpret_cast<uint4*>(base + 3 * TILE_E + so1) =                 \
            *reinterpret_cast<const uint4*>(Wl + gW1 + koff);                \
    } while (0)

    const int arow = wm * 32 + (lane & 15);
    const int acol = (lane >> 4) << 3;
    const int brow = wn * 64 + ((lane & 7) | ((lane & 16) >> 1));
    const int bcol = lane & 8;

    float acc[2][8][4];
#pragma unroll
    for (int i = 0; i < 2; i++)
#pragma unroll
        for (int j = 0; j < 8; j++)
#pragma unroll
            for (int c = 0; c < 4; c++) acc[i][j][c] = 0.f;

    const int nchunk = K >> 5;

    LOAD_CHUNK(0, 0);
    __syncthreads();

    for (int kc = 0; kc < nchunk; kc++) {
        /* issue next chunk's LDG+STS; its completion is only needed at
           the sync below — current chunk's MMAs (independent) fill the gap.
           The second CTA on this SM covers any residual stall.          */
        if (kc + 1 < nchunk) LOAD_CHUNK(kc + 1, (kc + 1) & 1);

        const uint32_t st  = sb + (uint32_t)(kc & 1) * 4 * TILE_E * 2;
        const uint32_t sAh = st;
        const uint32_t sAl = st + 1 * TILE_E * 2;
        const uint32_t sWh = st + 2 * TILE_E * 2;
        const uint32_t sWl = st + 3 * TILE_E * 2;

#pragma unroll
        for (int ks = 0; ks < 2; ks++) {
            const uint32_t aoff = 2u * ((uint32_t)(arow * TSTR) + ks * 16 + acol);
            uint32_t ah[2][4], al[2][4];
#pragma unroll
            for (int mt = 0; mt < 2; mt++) {
                uint32_t d = aoff + 2u * (mt * 16 * TSTR);
                ldsm4(sAh + d, ah[mt][0], ah[mt][1], ah[mt][2], ah[mt][3]);
                ldsm4(sAl + d, al[mt][0], al[mt][1], al[mt][2], al[mt][3]);
            }
#pragma unroll
            for (int np = 0; np < 4; np++) {
                const uint32_t boff =
                    2u * ((uint32_t)((brow + np * 16) * TSTR) + ks * 16 + bcol);
                uint32_t bh[4], bl[4];
                ldsm4(sWh + boff, bh[0], bh[1], bh[2], bh[3]);
                ldsm4(sWl + boff, bl[0], bl[1], bl[2], bl[3]);
#pragma unroll
                for (int mt = 0; mt < 2; mt++) {
#pragma unroll
                    for (int sub = 0; sub < 2; sub++) {
                        float* c = acc[mt][np * 2 + sub];
                        mma16816(c, ah[mt][0], ah[mt][1], ah[mt][2], ah[mt][3],
                                 bh[sub * 2], bh[sub * 2 + 1]);
                        mma16816(c, ah[mt][0], ah[mt][1], ah[mt][2], ah[mt][3],
                                 bl[sub * 2], bl[sub * 2 + 1]);
                        mma16816(c, al[mt][0], al[mt][1], al[mt][2], al[mt][3],
                                 bh[sub * 2], bh[sub * 2 + 1]);
                    }
                }
            }
        }
        __syncthreads();
    }

    /* epilogue */
    const int grp = lane >> 2;
    const int qid = lane & 3;
#pragma unroll
    for (int mt = 0; mt < 2; mt++) {
#pragma unroll
        for (int nt = 0; nt < 8; nt++) {
            const float* c = acc[mt][nt];
            int row = m0 + wm * 32 + mt * 16 + grp;
            int col = j0 + wn * 64 + nt * 8 + qid * 2;
#pragma unroll
            for (int half = 0; half < 2; half++) {
                int m = row + half * 8;
                float vx = c[half * 2], vy = c[half * 2 + 1];
                if (MODE == 0) {
                    int s  = col >> 10;
                    int rr = col & 1023;
                    int h  = rr >> 6;
                    int dh = rr & 63;
                    int b  = m >> 11;
                    int n  = m & 2047;
                    size_t idx = (((size_t)(b * H_ + h) * N_ + n) * DH_ + dh);
                    float sc = (s == 0) ? SCALE_ : 1.f;
                    uint32_t hi, lo;
                    split2(vx * sc, vy * sc, hi, lo);
                    __nv_bfloat16* bhp = (s == 0) ? g_qh : (s == 1) ? g_kh : g_vh;
                    __nv_bfloat16* blp = (s == 0) ? g_ql : (s == 1) ? g_kl : g_vl;
                    *reinterpret_cast<uint32_t*>(bhp + idx) = hi;
                    *reinterpret_cast<uint32_t*>(blp + idx) = lo;
                } else {
                    *reinterpret_cast<float2*>(C + (size_t)m * Nout + col) =
                        make_float2(vx, vy);
                }
            }
        }
    }
}

/* ------------------------------------------------------------------ */
/* Flash-attention on HMMA, inputs pre-split bf16 hi/lo. 2 CTAs/SM.    */
/* ------------------------------------------------------------------ */
#define ASTR 72
#define SM_QH 0
#define SM_QL (128 * ASTR)
#define SM_KH (2 * 128 * ASTR)
#define SM_KL (SM_KH + 64 * ASTR)
#define SM_VH (SM_KL + 64 * ASTR)
#define SM_VL (SM_VH + 64 * ASTR)
#define ATT_SMEM_ELEMS (SM_VL + 64 * ASTR)   /* 36864 bf16 = 73728 B */

__global__ void __launch_bounds__(256, 2)
attn_mma()
{
    extern __shared__ __nv_bfloat16 sbuf[];
    __nv_bfloat16* QH = sbuf + SM_QH;
    __nv_bfloat16* QL = sbuf + SM_QL;
    __nv_bfloat16* KH = sbuf + SM_KH;
    __nv_bfloat16* KL = sbuf + SM_KL;
    __nv_bfloat16* VH = sbuf + SM_VH;
    __nv_bfloat16* VL = sbuf + SM_VL;

    const int qt = (N_ / 128 - 1) - (blockIdx.x >> 5);  /* heavy tiles first */
    const int bh = blockIdx.x & 31;
    const int b  = bh >> 4;
    const int h  = bh & 15;

    const int tid  = threadIdx.x;
    const int lane = tid & 31;
    const int w    = tid >> 5;

    const __nv_bfloat16* Qbh = g_qh + (size_t)bh * N_ * DH_;
    const __nv_bfloat16* Qbl = g_ql + (size_t)bh * N_ * DH_;
    const __nv_bfloat16* Kbh = g_kh + (size_t)bh * N_ * DH_;
    const __nv_bfloat16* Kbl = g_kl + (size_t)bh * N_ * DH_;
    const __nv_bfloat16* Vbh = g_vh + (size_t)bh * N_ * DH_;
    const __nv_bfloat16* Vbl = g_vl + (size_t)bh * N_ * DH_;

    /* ---- load Q tile (pre-scaled, pre-split) ---- */
#pragma unroll
    for (int it = 0; it < 4; it++) {
        int idx = tid + it * 256;
        int r   = idx >> 3;
        int c8  = (idx & 7) * 8;
        size_t g = (size_t)(qt * 128 + r) * DH_ + c8;
        *reinterpret_cast<uint4*>(QH + r * ASTR + c8) =
            *reinterpret_cast<const uint4*>(Qbh + g);
        *reinterpret_cast<uint4*>(QL + r * ASTR + c8) =
            *reinterpret_cast<const uint4*>(Qbl + g);
    }
    __syncthreads();

    const uint32_t sQH = smem_u32(QH);
    const uint32_t sQL = smem_u32(QL);
    const uint32_t sKH = smem_u32(KH);
    const uint32_t sKL = smem_u32(KL);
    const uint32_t sVH = smem_u32(VH);
    const uint32_t sVL = smem_u32(VL);

    /* ---- Q fragments into registers ---- */
    uint32_t qh[4][4], ql[4][4];
    {
        const uint32_t a0 =
            2u * ((uint32_t)((w * 16 + (lane & 15)) * ASTR) + ((lane >> 4) << 3));
#pragma unroll
        for (int ks = 0; ks < 4; ks++) {
            ldsm4(sQH + a0 + 2u * (ks * 16), qh[ks][0], qh[ks][1], qh[ks][2], qh[ks][3]);
            ldsm4(sQL + a0 + 2u * (ks * 16), ql[ks][0], ql[ks][1], ql[ks][2], ql[ks][3]);
        }
    }

    const uint32_t bpat = 2u * ((uint32_t)(((lane & 7) | ((lane & 16) >> 1)) * ASTR)
                                + (lane & 8));

    float o[8][4];
#pragma unroll
    for (int i = 0; i < 8; i++)
#pragma unroll
        for (int c = 0; c < 4; c++) o[i][c] = 0.f;
    float mrow0 = -INFINITY, mrow1 = -INFINITY;
    float lrow0 = 0.f, lrow1 = 0.f;

    const int qglo   = qt * 128 + w * 16;
    const int ntiles = 2 * qt + 2;

    for (int jt = 0; jt < ntiles; jt++) {
        __syncthreads();
#pragma unroll
        for (int it = 0; it < 2; it++) {
            int idx = tid + it * 256;
            int r   = idx >> 3;
            int c8  = (idx & 7) * 8;
            size_t g = (size_t)(jt * 64 + r) * DH_ + c8;
            *reinterpret_cast<uint4*>(KH + r * ASTR + c8) =
                *reinterpret_cast<const uint4*>(Kbh + g);
            *reinterpret_cast<uint4*>(KL + r * ASTR + c8) =
                *reinterpret_cast<const uint4*>(Kbl + g);
        }
#pragma unroll
        for (int it = 0; it < 2; it++) {
            int idx = tid + it * 256;
            int j   = idx >> 3;
            int d8  = (idx & 7) * 8;
            size_t g = (size_t)(jt * 64 + j) * DH_ + d8;
            uint4 wh = *reinterpret_cast<const uint4*>(Vbh + g);
            uint4 wl = *reinterpret_cast<const uint4*>(Vbl + g);
            const __nv_bfloat16* ph = reinterpret_cast<const __nv_bfloat16*>(&wh);
            const __nv_bfloat16* pl = reinterpret_cast<const __nv_bfloat16*>(&wl);
#pragma unroll
            for (int e = 0; e < 8; e++) {
                VH[(d8 + e) * ASTR + j] = ph[e];
                VL[(d8 + e) * ASTR + j] = pl[e];
            }
        }
        __syncthreads();

        if (jt * 64 > qglo + 15) continue;

        /* ---- S = Q K^T ---- */
        float s[8][4];
#pragma unroll
        for (int i = 0; i < 8; i++)
#pragma unroll
            for (int c = 0; c < 4; c++) s[i][c] = 0.f;

#pragma unroll
        for (int ks = 0; ks < 4; ks++) {
#pragma unroll
            for (int np = 0; np < 4; np++) {
                const uint32_t boff = bpat + 2u * (np * 16 * ASTR + ks * 16);
                uint32_t bh4[4], bl4[4];
                ldsm4(sKH + boff, bh4[0], bh4[1], bh4[2], bh4[3]);
                ldsm4(sKL + boff, bl4[0], bl4[1], bl4[2], bl4[3]);
#pragma unroll
                for (int sub = 0; sub < 2; sub++) {
                    float* c = s[np * 2 + sub];
                    mma16816(c, qh[ks][0], qh[ks][1], qh[ks][2], qh[ks][3],
                             bh4[sub * 2], bh4[sub * 2 + 1]);
                    mma16816(c, qh[ks][0], qh[ks][1], qh[ks][2], qh[ks][3],
                             bl4[sub * 2], bl4[sub * 2 + 1]);
                    mma16816(c, ql[ks][0], ql[ks][1], ql[ks][2], ql[ks][3],
                             bh4[sub * 2], bh4[sub * 2 + 1]);
                }
            }
        }

        /* ---- causal mask ---- */
        const int r0 = qglo + (lane >> 2);
        const int r1 = r0 + 8;
        if (jt * 64 + 63 > qglo) {
            const int colb = jt * 64 + (lane & 3) * 2;
#pragma unroll
            for (int nt = 0; nt < 8; nt++) {
                int c0 = colb + nt * 8;
                if (c0 > r0)     s[nt][0] = -INFINITY;
                if (c0 + 1 > r0) s[nt][1] = -INFINITY;
                if (c0 > r1)     s[nt][2] = -INFINITY;
                if (c0 + 1 > r1) s[nt][3] = -INFINITY;
            }
        }

        /* ---- online softmax ---- */
        float mt0 = s[0][0], mt1 = s[0][2];
#pragma unroll
        for (int nt = 0; nt < 8; nt++) {
            mt0 = fmaxf(mt0, fmaxf(s[nt][0], s[nt][1]));
            mt1 = fmaxf(mt1, fmaxf(s[nt][2], s[nt][3]));
        }
        mt0 = fmaxf(mt0, __shfl_xor_sync(0xffffffffu, mt0, 1));
        mt0 = fmaxf(mt0, __shfl_xor_sync(0xffffffffu, mt0, 2));
        mt1 = fmaxf(mt1, __shfl_xor_sync(0xffffffffu, mt1, 1));
        mt1 = fmaxf(mt1, __shfl_xor_sync(0xffffffffu, mt1, 2));

        const float mn0 = fmaxf(mrow0, mt0);
        const float mn1 = fmaxf(mrow1, mt1);
        const float al0 = __expf(mrow0 - mn0);
        const float al1 = __expf(mrow1 - mn1);

        float ps0 = 0.f, ps1 = 0.f;
#pragma unroll
        for (int nt = 0; nt < 8; nt++) {
            s[nt][0] = __expf(s[nt][0] - mn0);
            s[nt][1] = __expf(s[nt][1] - mn0);
            s[nt][2] = __expf(s[nt][2] - mn1);
            s[nt][3] = __expf(s[nt][3] - mn1);
            ps0 += s[nt][0] + s[nt][1];
            ps1 += s[nt][2] + s[nt][3];
        }
        ps0 += __shfl_xor_sync(0xffffffffu, ps0, 1);
        ps0 += __shfl_xor_sync(0xffffffffu, ps0, 2);
        ps1 += __shfl_xor_sync(0xffffffffu, ps1, 1);
        ps1 += __shfl_xor_sync(0xffffffffu, ps1, 2);

        lrow0 = lrow0 * al0 + ps0;
        lrow1 = lrow1 * al1 + ps1;
#pragma unroll
        for (int nt = 0; nt < 8; nt++) {
            o[nt][0] *= al0; o[nt][1] *= al0;
            o[nt][2] *= al1; o[nt][3] *= al1;
        }
        mrow0 = mn0;
        mrow1 = mn1;

        /* ---- O += P V ---- */
#pragma unroll
        for (int ks = 0; ks < 4; ks++) {
            uint32_t ph[4], pl[4];
            split2(s[2 * ks][0],     s[2 * ks][1],     ph[0], pl[0]);
            split2(s[2 * ks][2],     s[2 * ks][3],     ph[1], pl[1]);
            split2(s[2 * ks + 1][0], s[2 * ks + 1][1], ph[2], pl[2]);
            split2(s[2 * ks + 1][2], s[2 * ks + 1][3], ph[3], pl[3]);
#pragma unroll
            for (int np = 0; np < 4; np++) {
                const uint32_t boff = bpat + 2u * (np * 16 * ASTR + ks * 16);
                uint32_t bh4[4], bl4[4];
                ldsm4(sVH + boff, bh4[0], bh4[1], bh4[2], bh4[3]);
                ldsm4(sVL + boff, bl4[0], bl4[1], bl4[2], bl4[3]);
#pragma unroll
                for (int sub = 0; sub < 2; sub++) {
                    float* c = o[np * 2 + sub];
                    mma16816(c, ph[0], ph[1], ph[2], ph[3],
                             bh4[sub * 2], bh4[sub * 2 + 1]);
                    mma16816(c, ph[0], ph[1], ph[2], ph[3],
                             bl4[sub * 2], bl4[sub * 2 + 1]);
                    mma16816(c, pl[0], pl[1], pl[2], pl[3],
                             bh4[sub * 2], bh4[sub * 2 + 1]);
                }
            }
        }
    }

    /* ---- epilogue ---- */
    const float i0 = 1.f / lrow0;
    const float i1 = 1.f / lrow1;
    const int r0 = qt * 128 + w * 16 + (lane >> 2);
    const size_t base0 = ((size_t)b * N_ + r0) * D_ + h * DH_ + (lane & 3) * 2;
    const size_t base1 = base0 + 8 * D_;
#pragma unroll
    for (int nt = 0; nt < 8; nt++) {
        uint32_t hi, lo;
        split2(o[nt][0] * i0, o[nt][1] * i0, hi, lo);
        *reinterpret_cast<uint32_t*>(g_aoh + base0 + nt * 8) = hi;
        *reinterpret_cast<uint32_t*>(g_aol + base0 + nt * 8) = lo;
        split2(o[nt][2] * i1, o[nt][3] * i1, hi, lo);
        *reinterpret_cast<uint32_t*>(g_aoh + base1 + nt * 8) = hi;
        *reinterpret_cast<uint32_t*>(g_aol + base1 + nt * 8) = lo;
    }
}

/* ------------------------------------------------------------------ */
extern "C" void kernel_launch(void* const* d_in, const int* in_sizes, int n_in,
                              void* d_out, int out_size)
{
    const float* x    = (const float*)d_in[0];
    /* d_in[1] = mask (static causal structure, unused) */
    const float* Wqkv = (const float*)d_in[2];
    const float* Wout = (const float*)d_in[3];
    float* out = (float*)d_out;

    __nv_bfloat16 *xh, *xl, *wqh, *wql, *woh, *wol, *aoh, *aol;
    cudaGetSymbolAddress((void**)&xh,  g_xh);
    cudaGetSymbolAddress((void**)&xl,  g_xl);
    cudaGetSymbolAddress((void**)&wqh, g_wqh);
    cudaGetSymbolAddress((void**)&wql, g_wql);
    cudaGetSymbolAddress((void**)&woh, g_woh);
    cudaGetSymbolAddress((void**)&wol, g_wol);
    cudaGetSymbolAddress((void**)&aoh, g_aoh);
    cudaGetSymbolAddress((void**)&aol, g_aol);

    /* 0. split inputs to bf16 hi/lo */
    split_fp32<<<1024, 256>>>(x,    xh,  xl,  4096 * 1024 / 4);
    split_fp32<<<1024, 256>>>(Wqkv, wqh, wql, 3072 * 1024 / 4);
    split_fp32<<<512,  256>>>(Wout, woh, wol, 1024 * 1024 / 4);

    cudaFuncSetAttribute(gemm_bf16<0>,
                         cudaFuncAttributeMaxDynamicSharedMemorySize, GEMM_SMEM);
    cudaFuncSetAttribute(gemm_bf16<1>,
                         cudaFuncAttributeMaxDynamicSharedMemorySize, GEMM_SMEM);

    /* 1. QKV projection -> q/k/v hi/lo (q pre-scaled) */
    gemm_bf16<0><<<dim3(3072 / 128, 4096 / 128), 256, GEMM_SMEM>>>(
        xh, xl, wqh, wql, nullptr, D_, 3 * D_);

    /* 2. causal flash attention -> ao hi/lo */
    const int ATT_SMEM = ATT_SMEM_ELEMS * (int)sizeof(__nv_bfloat16);
    cudaFuncSetAttribute(attn_mma,
                         cudaFuncAttributeMaxDynamicSharedMemorySize, ATT_SMEM);
    attn_mma<<<dim3((N_ / 128) * 32), 256, ATT_SMEM>>>();

    /* 3. output projection -> d_out (fp32) */
    gemm_bf16<1><<<dim3(1024 / 128, 4096 / 128), 256, GEMM_SMEM>>>(
        aoh, aol, woh, wol, out, D_, D_);
}

// round 8
// speedup vs baseline: 1.9478x; 1.1783x over previous
#include <cuda_runtime.h>
#include <cuda_bf16.h>
#include <math.h>
#include <stdint.h>

#define B_ 2
#define N_ 2048
#define D_ 1024
#define H_ 16
#define DH_ 64
#define SCALE_ 0.125f   /* 64^-0.5, exact power of two */

/* ------------------------------------------------------------------ */
/* device scratch: everything bf16 hi/lo pairs                         */
/* ------------------------------------------------------------------ */
__device__ __nv_bfloat16 g_xh [4096 * 1024], g_xl [4096 * 1024];
__device__ __nv_bfloat16 g_wqh[3072 * 1024], g_wql[3072 * 1024];
__device__ __nv_bfloat16 g_woh[1024 * 1024], g_wol[1024 * 1024];
__device__ __nv_bfloat16 g_qh [B_*H_*N_*DH_], g_ql [B_*H_*N_*DH_];
__device__ __nv_bfloat16 g_kh [B_*H_*N_*DH_], g_kl [B_*H_*N_*DH_];
__device__ __nv_bfloat16 g_vh [B_*H_*N_*DH_], g_vl [B_*H_*N_*DH_];
__device__ __nv_bfloat16 g_aoh[B_*N_*D_],     g_aol[B_*N_*D_];

/* ------------------------------------------------------------------ */
/* helpers                                                             */
/* ------------------------------------------------------------------ */
__device__ __forceinline__ uint32_t smem_u32(const void* p) {
    uint32_t a;
    asm("{ .reg .u64 t; cvta.to.shared.u64 t, %1; cvt.u32.u64 %0, t; }"
        : "=r"(a) : "l"(p));
    return a;
}

__device__ __forceinline__ void ldsm4(uint32_t addr, uint32_t& r0, uint32_t& r1,
                                      uint32_t& r2, uint32_t& r3) {
    asm volatile("ldmatrix.sync.aligned.m8n8.x4.shared.b16 {%0,%1,%2,%3}, [%4];"
                 : "=r"(r0), "=r"(r1), "=r"(r2), "=r"(r3) : "r"(addr));
}

__device__ __forceinline__ void ldsm4t(uint32_t addr, uint32_t& r0, uint32_t& r1,
                                       uint32_t& r2, uint32_t& r3) {
    asm volatile("ldmatrix.sync.aligned.m8n8.x4.trans.shared.b16 {%0,%1,%2,%3}, [%4];"
                 : "=r"(r0), "=r"(r1), "=r"(r2), "=r"(r3) : "r"(addr));
}

__device__ __forceinline__ void mma16816(float* c,
                                         uint32_t a0, uint32_t a1, uint32_t a2, uint32_t a3,
                                         uint32_t b0, uint32_t b1) {
    asm volatile(
        "mma.sync.aligned.m16n8k16.row.col.f32.bf16.bf16.f32 "
        "{%0,%1,%2,%3}, {%4,%5,%6,%7}, {%8,%9}, {%0,%1,%2,%3};"
        : "+f"(c[0]), "+f"(c[1]), "+f"(c[2]), "+f"(c[3])
        : "r"(a0), "r"(a1), "r"(a2), "r"(a3), "r"(b0), "r"(b1));
}

__device__ __forceinline__ void split2(float x, float y, uint32_t& hi, uint32_t& lo) {
    __nv_bfloat162 h = __floats2bfloat162_rn(x, y);
    float rx = x - __bfloat162float(h.x);
    float ry = y - __bfloat162float(h.y);
    __nv_bfloat162 l = __floats2bfloat162_rn(rx, ry);
    hi = *reinterpret_cast<uint32_t*>(&h);
    lo = *reinterpret_cast<uint32_t*>(&l);
}

__device__ __forceinline__ void cp16(uint32_t saddr, const void* g) {
    asm volatile("cp.async.cg.shared.global [%0], [%1], 16;"
                 :: "r"(saddr), "l"(g) : "memory");
}
__device__ __forceinline__ void cp_commit() {
    asm volatile("cp.async.commit_group;" ::: "memory");
}
__device__ __forceinline__ void cp_wait0() {
    asm volatile("cp.async.wait_group 0;" ::: "memory");
}

/* ------------------------------------------------------------------ */
/* split kernel: fp32 -> bf16 hi/lo pair                               */
/* ------------------------------------------------------------------ */
__global__ void __launch_bounds__(256)
split_fp32(const float* __restrict__ src, __nv_bfloat16* __restrict__ h,
           __nv_bfloat16* __restrict__ l, int n4)
{
    int i      = blockIdx.x * blockDim.x + threadIdx.x;
    int stride = gridDim.x * blockDim.x;
    for (; i < n4; i += stride) {
        float4 v = reinterpret_cast<const float4*>(src)[i];
        uint32_t h0, l0, h1, l1;
        split2(v.x, v.y, h0, l0);
        split2(v.z, v.w, h1, l1);
        reinterpret_cast<uint2*>(h)[i] = make_uint2(h0, h1);
        reinterpret_cast<uint2*>(l)[i] = make_uint2(l0, l1);
    }
}

/* ------------------------------------------------------------------ */
/* HMMA GEMM on pre-split bf16: C = A * W^T.                           */
/* tile 128x128, BK=32, 256 thr (8 warps 4x2), 2 CTAs/SM.              */
/* cp.async double buffer: chunk kc+1 streams during MMA of kc.        */
/* ------------------------------------------------------------------ */
#define TSTR 40
#define TILE_E (128 * TSTR)                    /* bf16 elems per array */
#define GEMM_SMEM (2 * 4 * TILE_E * 2)         /* 81920 B dynamic      */

template <int MODE>
__global__ void __launch_bounds__(256, 2)
gemm_bf16(const __nv_bfloat16* __restrict__ Ah, const __nv_bfloat16* __restrict__ Al,
          const __nv_bfloat16* __restrict__ Wh, const __nv_bfloat16* __restrict__ Wl,
          float* __restrict__ C, int K, int Nout)
{
    extern __shared__ __nv_bfloat16 smem[];
    const uint32_t sb = smem_u32(smem);

    const int tid  = threadIdx.x;
    const int lane = tid & 31;
    const int wid  = tid >> 5;
    const int wm   = wid & 3;
    const int wn   = wid >> 2;

    const int m0 = blockIdx.y * 128;
    const int j0 = blockIdx.x * 128;

    /* per-thread copy slots */
    const int row0 = tid >> 2;
    const int row1 = (tid + 256) >> 2;
    const int q0   = tid & 3;
    const size_t gA0 = (size_t)(m0 + row0) * K + q0 * 8;
    const size_t gA1 = (size_t)(m0 + row1) * K + q0 * 8;
    const size_t gW0 = (size_t)(j0 + row0) * K + q0 * 8;
    const size_t gW1 = (size_t)(j0 + row1) * K + q0 * 8;
    const uint32_t so0 = (uint32_t)(row0 * TSTR + q0 * 8) * 2;  /* bytes */
    const uint32_t so1 = (uint32_t)(row1 * TSTR + q0 * 8) * 2;

#define ISSUE_CHUNK(kc, stage)                                                \
    do {                                                                      \
        const int koff = (kc) * 32;                                          \
        const uint32_t st_ = sb + (uint32_t)(stage) * 4 * TILE_E * 2;        \
        cp16(st_ + 0 * TILE_E * 2 + so0, Ah + gA0 + koff);                   \
        cp16(st_ + 0 * TILE_E * 2 + so1, Ah + gA1 + koff);                   \
        cp16(st_ + 1 * TILE_E * 2 + so0, Al + gA0 + koff);                   \
        cp16(st_ + 1 * TILE_E * 2 + so1, Al + gA1 + koff);                   \
        cp16(st_ + 2 * TILE_E * 2 + so0, Wh + gW0 + koff);                   \
        cp16(st_ + 2 * TILE_E * 2 + so1, Wh + gW1 + koff);                   \
        cp16(st_ + 3 * TILE_E * 2 + so0, Wl + gW0 + koff);                   \
        cp16(st_ + 3 * TILE_E * 2 + so1, Wl + gW1 + koff);                   \
        cp_commit();                                                         \
    } while (0)

    const int arow = wm * 32 + (lane & 15);
    const int acol = (lane >> 4) << 3;
    const int brow = wn * 64 + ((lane & 7) | ((lane & 16) >> 1));
    const int bcol = lane & 8;

    float acc[2][8][4];
#pragma unroll
    for (int i = 0; i < 2; i++)
#pragma unroll
        for (int j = 0; j < 8; j++)
#pragma unroll
            for (int c = 0; c < 4; c++) acc[i][j][c] = 0.f;

    const int nchunk = K >> 5;

    ISSUE_CHUNK(0, 0);

    for (int kc = 0; kc < nchunk; kc++) {
        cp_wait0();            /* only chunk kc's group is pending here */
        __syncthreads();       /* all threads' copies visible; stage reuse safe */
        if (kc + 1 < nchunk) ISSUE_CHUNK(kc + 1, (kc + 1) & 1);

        const uint32_t st  = sb + (uint32_t)(kc & 1) * 4 * TILE_E * 2;
        const uint32_t sAh = st;
        const uint32_t sAl = st + 1 * TILE_E * 2;
        const uint32_t sWh = st + 2 * TILE_E * 2;
        const uint32_t sWl = st + 3 * TILE_E * 2;

#pragma unroll
        for (int ks = 0; ks < 2; ks++) {
            const uint32_t aoff = 2u * ((uint32_t)(arow * TSTR) + ks * 16 + acol);
            uint32_t ah[2][4], al[2][4];
#pragma unroll
            for (int mt = 0; mt < 2; mt++) {
                uint32_t d = aoff + 2u * (mt * 16 * TSTR);
                ldsm4(sAh + d, ah[mt][0], ah[mt][1], ah[mt][2], ah[mt][3]);
                ldsm4(sAl + d, al[mt][0], al[mt][1], al[mt][2], al[mt][3]);
            }
#pragma unroll
            for (int np = 0; np < 4; np++) {
                const uint32_t boff =
                    2u * ((uint32_t)((brow + np * 16) * TSTR) + ks * 16 + bcol);
                uint32_t bh[4], bl[4];
                ldsm4(sWh + boff, bh[0], bh[1], bh[2], bh[3]);
                ldsm4(sWl + boff, bl[0], bl[1], bl[2], bl[3]);
#pragma unroll
                for (int mt = 0; mt < 2; mt++) {
#pragma unroll
                    for (int sub = 0; sub < 2; sub++) {
                        float* c = acc[mt][np * 2 + sub];
                        mma16816(c, ah[mt][0], ah[mt][1], ah[mt][2], ah[mt][3],
                                 bh[sub * 2], bh[sub * 2 + 1]);
                        mma16816(c, ah[mt][0], ah[mt][1], ah[mt][2], ah[mt][3],
                                 bl[sub * 2], bl[sub * 2 + 1]);
                        mma16816(c, al[mt][0], al[mt][1], al[mt][2], al[mt][3],
                                 bh[sub * 2], bh[sub * 2 + 1]);
                    }
                }
            }
        }
    }

    /* epilogue */
    const int grp = lane >> 2;
    const int qid = lane & 3;
#pragma unroll
    for (int mt = 0; mt < 2; mt++) {
#pragma unroll
        for (int nt = 0; nt < 8; nt++) {
            const float* c = acc[mt][nt];
            int row = m0 + wm * 32 + mt * 16 + grp;
            int col = j0 + wn * 64 + nt * 8 + qid * 2;
#pragma unroll
            for (int half = 0; half < 2; half++) {
                int m = row + half * 8;
                float vx = c[half * 2], vy = c[half * 2 + 1];
                if (MODE == 0) {
                    int s  = col >> 10;
                    int rr = col & 1023;
                    int h  = rr >> 6;
                    int dh = rr & 63;
                    int b  = m >> 11;
                    int n  = m & 2047;
                    size_t idx = (((size_t)(b * H_ + h) * N_ + n) * DH_ + dh);
                    float sc = (s == 0) ? SCALE_ : 1.f;
                    uint32_t hi, lo;
                    split2(vx * sc, vy * sc, hi, lo);
                    __nv_bfloat16* bhp = (s == 0) ? g_qh : (s == 1) ? g_kh : g_vh;
                    __nv_bfloat16* blp = (s == 0) ? g_ql : (s == 1) ? g_kl : g_vl;
                    *reinterpret_cast<uint32_t*>(bhp + idx) = hi;
                    *reinterpret_cast<uint32_t*>(blp + idx) = lo;
                } else {
                    *reinterpret_cast<float2*>(C + (size_t)m * Nout + col) =
                        make_float2(vx, vy);
                }
            }
        }
    }
}

/* ------------------------------------------------------------------ */
/* Flash-attention. K/V double-buffered via cp.async; V row-major,     */
/* B-fragments via ldmatrix.trans. 2 CTAs/SM.                          */
/* smem elems: Q 2*128*72 + 2 stages * 4 arrays * 64*72 = 55296        */
/* ------------------------------------------------------------------ */
#define ASTR 72
#define SM_QH 0
#define SM_QL (128 * ASTR)
#define SM_ST0 (2 * 128 * ASTR)            /* stage block start        */
#define STG_E  (4 * 64 * ASTR)             /* elems per stage block    */
#define OFF_KH 0
#define OFF_KL (64 * ASTR)
#define OFF_VH (2 * 64 * ASTR)
#define OFF_VL (3 * 64 * ASTR)
#define ATT_SMEM_ELEMS (SM_ST0 + 2 * STG_E)   /* 55296 bf16 = 110592 B */

__global__ void __launch_bounds__(256, 2)
attn_mma()
{
    extern __shared__ __nv_bfloat16 sbuf[];

    const int qt = (N_ / 128 - 1) - (blockIdx.x >> 5);  /* heavy tiles first */
    const int bh = blockIdx.x & 31;
    const int b  = bh >> 4;
    const int h  = bh & 15;

    const int tid  = threadIdx.x;
    const int lane = tid & 31;
    const int w    = tid >> 5;

    const __nv_bfloat16* Qbh = g_qh + (size_t)bh * N_ * DH_;
    const __nv_bfloat16* Qbl = g_ql + (size_t)bh * N_ * DH_;
    const __nv_bfloat16* Kbh = g_kh + (size_t)bh * N_ * DH_;
    const __nv_bfloat16* Kbl = g_kl + (size_t)bh * N_ * DH_;
    const __nv_bfloat16* Vbh = g_vh + (size_t)bh * N_ * DH_;
    const __nv_bfloat16* Vbl = g_vl + (size_t)bh * N_ * DH_;

    const uint32_t sB = smem_u32(sbuf);

    /* per-thread kv copy slots: idx = tid + it*256; r = idx>>3, c8=(idx&7)*8 */
    const int kr0 = tid >> 3;
    const int kr1 = (tid + 256) >> 3;
    const int kc8 = (tid & 7) * 8;
    const uint32_t kso0 = (uint32_t)(kr0 * ASTR + kc8) * 2;
    const uint32_t kso1 = (uint32_t)(kr1 * ASTR + kc8) * 2;

#define ISSUE_KV(jt, stage)                                                   \
    do {                                                                      \
        const size_t g0 = (size_t)((jt) * 64 + kr0) * DH_ + kc8;             \
        const size_t g1 = (size_t)((jt) * 64 + kr1) * DH_ + kc8;             \
        const uint32_t st_ = sB + (SM_ST0 + (stage) * STG_E) * 2;            \
        cp16(st_ + OFF_KH * 2 + kso0, Kbh + g0);                             \
        cp16(st_ + OFF_KH * 2 + kso1, Kbh + g1);                             \
        cp16(st_ + OFF_KL * 2 + kso0, Kbl + g0);                             \
        cp16(st_ + OFF_KL * 2 + kso1, Kbl + g1);                             \
        cp16(st_ + OFF_VH * 2 + kso0, Vbh + g0);                             \
        cp16(st_ + OFF_VH * 2 + kso1, Vbh + g1);                             \
        cp16(st_ + OFF_VL * 2 + kso0, Vbl + g0);                             \
        cp16(st_ + OFF_VL * 2 + kso1, Vbl + g1);                             \
        cp_commit();                                                         \
    } while (0)

    ISSUE_KV(0, 0);

    /* ---- load Q tile (pre-scaled, pre-split) ---- */
#pragma unroll
    for (int it = 0; it < 4; it++) {
        int idx = tid + it * 256;
        int r   = idx >> 3;
        int c8  = (idx & 7) * 8;
        size_t g = (size_t)(qt * 128 + r) * DH_ + c8;
        *reinterpret_cast<uint4*>(sbuf + SM_QH + r * ASTR + c8) =
            *reinterpret_cast<const uint4*>(Qbh + g);
        *reinterpret_cast<uint4*>(sbuf + SM_QL + r * ASTR + c8) =
            *reinterpret_cast<const uint4*>(Qbl + g);
    }
    __syncthreads();

    /* ---- Q fragments into registers ---- */
    uint32_t qh[4][4], ql[4][4];
    {
        const uint32_t a0 = sB +
            2u * ((uint32_t)((w * 16 + (lane & 15)) * ASTR) + ((lane >> 4) << 3));
#pragma unroll
        for (int ks = 0; ks < 4; ks++) {
            ldsm4(a0 + SM_QH * 2 + 2u * (ks * 16),
                  qh[ks][0], qh[ks][1], qh[ks][2], qh[ks][3]);
            ldsm4(a0 + SM_QL * 2 + 2u * (ks * 16),
                  ql[ks][0], ql[ks][1], ql[ks][2], ql[ks][3]);
        }
    }

    /* K fragment pattern (non-trans, same as R7) */
    const uint32_t bpat = 2u * ((uint32_t)(((lane & 7) | ((lane & 16) >> 1)) * ASTR)
                                + (lane & 8));
    /* V fragment pattern (trans): j = (lane&15), d-offset = (lane&16)>>1 */
    const uint32_t vpat = 2u * ((uint32_t)((lane & 15) * ASTR) + ((lane & 16) >> 1));

    float o[8][4];
#pragma unroll
    for (int i = 0; i < 8; i++)
#pragma unroll
        for (int c = 0; c < 4; c++) o[i][c] = 0.f;
    float mrow0 = -INFINITY, mrow1 = -INFINITY;
    float lrow0 = 0.f, lrow1 = 0.f;

    const int qglo   = qt * 128 + w * 16;
    const int ntiles = 2 * qt + 2;

    for (int jt = 0; jt < ntiles; jt++) {
        cp_wait0();          /* tile jt's copies (only pending group) */
        __syncthreads();     /* visibility + stage-reuse protection   */
        if (jt + 1 < ntiles) ISSUE_KV(jt + 1, (jt + 1) & 1);

        if (jt * 64 > qglo + 15) continue;   /* no further barriers below */

        const uint32_t stg = sB + (SM_ST0 + (jt & 1) * STG_E) * 2;
        const uint32_t sKH = stg + OFF_KH * 2;
        const uint32_t sKL = stg + OFF_KL * 2;
        const uint32_t sVH = stg + OFF_VH * 2;
        const uint32_t sVL = stg + OFF_VL * 2;

        /* ---- S = Q K^T ---- */
        float s[8][4];
#pragma unroll
        for (int i = 0; i < 8; i++)
#pragma unroll
            for (int c = 0; c < 4; c++) s[i][c] = 0.f;

#pragma unroll
        for (int ks = 0; ks < 4; ks++) {
#pragma unroll
            for (int np = 0; np < 4; np++) {
                const uint32_t boff = bpat + 2u * (np * 16 * ASTR + ks * 16);
                uint32_t bh4[4], bl4[4];
                ldsm4(sKH + boff, bh4[0], bh4[1], bh4[2], bh4[3]);
                ldsm4(sKL + boff, bl4[0], bl4[1], bl4[2], bl4[3]);
#pragma unroll
                for (int sub = 0; sub < 2; sub++) {
                    float* c = s[np * 2 + sub];
                    mma16816(c, qh[ks][0], qh[ks][1], qh[ks][2], qh[ks][3],
                             bh4[sub * 2], bh4[sub * 2 + 1]);
                    mma16816(c, qh[ks][0], qh[ks][1], qh[ks][2], qh[ks][3],
                             bl4[sub * 2], bl4[sub * 2 + 1]);
                    mma16816(c, ql[ks][0], ql[ks][1], ql[ks][2], ql[ks][3],
                             bh4[sub * 2], bh4[sub * 2 + 1]);
                }
            }
        }

        /* ---- causal mask ---- */
        const int r0 = qglo + (lane >> 2);
        const int r1 = r0 + 8;
        if (jt * 64 + 63 > qglo) {
            const int colb = jt * 64 + (lane & 3) * 2;
#pragma unroll
            for (int nt = 0; nt < 8; nt++) {
                int c0 = colb + nt * 8;
                if (c0 > r0)     s[nt][0] = -INFINITY;
                if (c0 + 1 > r0) s[nt][1] = -INFINITY;
                if (c0 > r1)     s[nt][2] = -INFINITY;
                if (c0 + 1 > r1) s[nt][3] = -INFINITY;
            }
        }

        /* ---- online softmax ---- */
        float mt0 = s[0][0], mt1 = s[0][2];
#pragma unroll
        for (int nt = 0; nt < 8; nt++) {
            mt0 = fmaxf(mt0, fmaxf(s[nt][0], s[nt][1]));
            mt1 = fmaxf(mt1, fmaxf(s[nt][2], s[nt][3]));
        }
        mt0 = fmaxf(mt0, __shfl_xor_sync(0xffffffffu, mt0, 1));
        mt0 = fmaxf(mt0, __shfl_xor_sync(0xffffffffu, mt0, 2));
        mt1 = fmaxf(mt1, __shfl_xor_sync(0xffffffffu, mt1, 1));
        mt1 = fmaxf(mt1, __shfl_xor_sync(0xffffffffu, mt1, 2));

        const float mn0 = fmaxf(mrow0, mt0);
        const float mn1 = fmaxf(mrow1, mt1);
        const float al0 = __expf(mrow0 - mn0);
        const float al1 = __expf(mrow1 - mn1);

        float ps0 = 0.f, ps1 = 0.f;
#pragma unroll
        for (int nt = 0; nt < 8; nt++) {
            s[nt][0] = __expf(s[nt][0] - mn0);
            s[nt][1] = __expf(s[nt][1] - mn0);
            s[nt][2] = __expf(s[nt][2] - mn1);
            s[nt][3] = __expf(s[nt][3] - mn1);
            ps0 += s[nt][0] + s[nt][1];
            ps1 += s[nt][2] + s[nt][3];
        }
        ps0 += __shfl_xor_sync(0xffffffffu, ps0, 1);
        ps0 += __shfl_xor_sync(0xffffffffu, ps0, 2);
        ps1 += __shfl_xor_sync(0xffffffffu, ps1, 1);
        ps1 += __shfl_xor_sync(0xffffffffu, ps1, 2);

        lrow0 = lrow0 * al0 + ps0;
        lrow1 = lrow1 * al1 + ps1;
#pragma unroll
        for (int nt = 0; nt < 8; nt++) {
            o[nt][0] *= al0; o[nt][1] *= al0;
            o[nt][2] *= al1; o[nt][3] *= al1;
        }
        mrow0 = mn0;
        mrow1 = mn1;

        /* ---- O += P V (V fragments via ldmatrix.trans) ---- */
#pragma unroll
        for (int ks = 0; ks < 4; ks++) {
            uint32_t ph[4], pl[4];
            split2(s[2 * ks][0],     s[2 * ks][1],     ph[0], pl[0]);
            split2(s[2 * ks][2],     s[2 * ks][3],     ph[1], pl[1]);
            split2(s[2 * ks + 1][0], s[2 * ks + 1][1], ph[2], pl[2]);
            split2(s[2 * ks + 1][2], s[2 * ks + 1][3], ph[3], pl[3]);
#pragma unroll
            for (int np = 0; np < 4; np++) {
                const uint32_t voff = vpat + 2u * (ks * 16 * ASTR + np * 16);
                uint32_t bh4[4], bl4[4];
                ldsm4t(sVH + voff, bh4[0], bh4[1], bh4[2], bh4[3]);
                ldsm4t(sVL + voff, bl4[0], bl4[1], bl4[2], bl4[3]);
#pragma unroll
                for (int sub = 0; sub < 2; sub++) {
                    float* c = o[np * 2 + sub];
                    mma16816(c, ph[0], ph[1], ph[2], ph[3],
                             bh4[sub * 2], bh4[sub * 2 + 1]);
                    mma16816(c, ph[0], ph[1], ph[2], ph[3],
                             bl4[sub * 2], bl4[sub * 2 + 1]);
                    mma16816(c, pl[0], pl[1], pl[2], pl[3],
                             bh4[sub * 2], bh4[sub * 2 + 1]);
                }
            }
        }
    }

    /* ---- epilogue ---- */
    const float i0 = 1.f / lrow0;
    const float i1 = 1.f / lrow1;
    const int r0 = qt * 128 + w * 16 + (lane >> 2);
    const size_t base0 = ((size_t)b * N_ + r0) * D_ + h * DH_ + (lane & 3) * 2;
    const size_t base1 = base0 + 8 * D_;
#pragma unroll
    for (int nt = 0; nt < 8; nt++) {
        uint32_t hi, lo;
        split2(o[nt][0] * i0, o[nt][1] * i0, hi, lo);
        *reinterpret_cast<uint32_t*>(g_aoh + base0 + nt * 8) = hi;
        *reinterpret_cast<uint32_t*>(g_aol + base0 + nt * 8) = lo;
        split2(o[nt][2] * i1, o[nt][3] * i1, hi, lo);
        *reinterpret_cast<uint32_t*>(g_aoh + base1 + nt * 8) = hi;
        *reinterpret_cast<uint32_t*>(g_aol + base1 + nt * 8) = lo;
    }
}

/* ------------------------------------------------------------------ */
extern "C" void kernel_launch(void* const* d_in, const int* in_sizes, int n_in,
                              void* d_out, int out_size)
{
    const float* x    = (const float*)d_in[0];
    /* d_in[1] = mask (static causal structure, unused) */
    const float* Wqkv = (const float*)d_in[2];
    const float* Wout = (const float*)d_in[3];
    float* out = (float*)d_out;

    __nv_bfloat16 *xh, *xl, *wqh, *wql, *woh, *wol, *aoh, *aol;
    cudaGetSymbolAddress((void**)&xh,  g_xh);
    cudaGetSymbolAddress((void**)&xl,  g_xl);
    cudaGetSymbolAddress((void**)&wqh, g_wqh);
    cudaGetSymbolAddress((void**)&wql, g_wql);
    cudaGetSymbolAddress((void**)&woh, g_woh);
    cudaGetSymbolAddress((void**)&wol, g_wol);
    cudaGetSymbolAddress((void**)&aoh, g_aoh);
    cudaGetSymbolAddress((void**)&aol, g_aol);

    /* 0. split inputs to bf16 hi/lo */
    split_fp32<<<1024, 256>>>(x,    xh,  xl,  4096 * 1024 / 4);
    split_fp32<<<1024, 256>>>(Wqkv, wqh, wql, 3072 * 1024 / 4);
    split_fp32<<<512,  256>>>(Wout, woh, wol, 1024 * 1024 / 4);

    cudaFuncSetAttribute(gemm_bf16<0>,
                         cudaFuncAttributeMaxDynamicSharedMemorySize, GEMM_SMEM);
    cudaFuncSetAttribute(gemm_bf16<1>,
                         cudaFuncAttributeMaxDynamicSharedMemorySize, GEMM_SMEM);

    /* 1. QKV projection -> q/k/v hi/lo (q pre-scaled) */
    gemm_bf16<0><<<dim3(3072 / 128, 4096 / 128), 256, GEMM_SMEM>>>(
        xh, xl, wqh, wql, nullptr, D_, 3 * D_);

    /* 2. causal flash attention -> ao hi/lo */
    const int ATT_SMEM = ATT_SMEM_ELEMS * (int)sizeof(__nv_bfloat16);  /* 110592 */
    cudaFuncSetAttribute(attn_mma,
                         cudaFuncAttributeMaxDynamicSharedMemorySize, ATT_SMEM);
    attn_mma<<<dim3((N_ / 128) * 32), 256, ATT_SMEM>>>();

    /* 3. output projection -> d_out (fp32) */
    gemm_bf16<1><<<dim3(1024 / 128, 4096 / 128), 256, GEMM_SMEM>>>(
        aoh, aol, woh, wol, out, D_, D_);
}

// round 9
// speedup vs baseline: 2.0253x; 1.0398x over previous
#include <cuda_runtime.h>
#include <cuda_bf16.h>
#include <math.h>
#include <stdint.h>

#define B_ 2
#define N_ 2048
#define D_ 1024
#define H_ 16
#define DH_ 64
#define SCALE_ 0.125f   /* 64^-0.5, exact power of two */

/* ------------------------------------------------------------------ */
/* device scratch: everything bf16 hi/lo pairs                         */
/* ------------------------------------------------------------------ */
__device__ __nv_bfloat16 g_xh [4096 * 1024], g_xl [4096 * 1024];
__device__ __nv_bfloat16 g_wqh[3072 * 1024], g_wql[3072 * 1024];
__device__ __nv_bfloat16 g_woh[1024 * 1024], g_wol[1024 * 1024];
__device__ __nv_bfloat16 g_qh [B_*H_*N_*DH_], g_ql [B_*H_*N_*DH_];
__device__ __nv_bfloat16 g_kh [B_*H_*N_*DH_], g_kl [B_*H_*N_*DH_];
__device__ __nv_bfloat16 g_vh [B_*H_*N_*DH_], g_vl [B_*H_*N_*DH_];
__device__ __nv_bfloat16 g_aoh[B_*N_*D_],     g_aol[B_*N_*D_];

/* ------------------------------------------------------------------ */
/* helpers                                                             */
/* ------------------------------------------------------------------ */
__device__ __forceinline__ uint32_t smem_u32(const void* p) {
    uint32_t a;
    asm("{ .reg .u64 t; cvta.to.shared.u64 t, %1; cvt.u32.u64 %0, t; }"
        : "=r"(a) : "l"(p));
    return a;
}

/* swizzle for 64B-row tiles: XOR row-pair bits into 16B-chunk index */
__device__ __forceinline__ uint32_t swz(uint32_t o) {
    return o ^ (((o >> 7) & 3u) << 4);
}

__device__ __forceinline__ void ldsm4(uint32_t addr, uint32_t& r0, uint32_t& r1,
                                      uint32_t& r2, uint32_t& r3) {
    asm volatile("ldmatrix.sync.aligned.m8n8.x4.shared.b16 {%0,%1,%2,%3}, [%4];"
                 : "=r"(r0), "=r"(r1), "=r"(r2), "=r"(r3) : "r"(addr));
}

__device__ __forceinline__ void ldsm4t(uint32_t addr, uint32_t& r0, uint32_t& r1,
                                       uint32_t& r2, uint32_t& r3) {
    asm volatile("ldmatrix.sync.aligned.m8n8.x4.trans.shared.b16 {%0,%1,%2,%3}, [%4];"
                 : "=r"(r0), "=r"(r1), "=r"(r2), "=r"(r3) : "r"(addr));
}

__device__ __forceinline__ void mma16816(float* c,
                                         uint32_t a0, uint32_t a1, uint32_t a2, uint32_t a3,
                                         uint32_t b0, uint32_t b1) {
    asm volatile(
        "mma.sync.aligned.m16n8k16.row.col.f32.bf16.bf16.f32 "
        "{%0,%1,%2,%3}, {%4,%5,%6,%7}, {%8,%9}, {%0,%1,%2,%3};"
        : "+f"(c[0]), "+f"(c[1]), "+f"(c[2]), "+f"(c[3])
        : "r"(a0), "r"(a1), "r"(a2), "r"(a3), "r"(b0), "r"(b1));
}

__device__ __forceinline__ void split2(float x, float y, uint32_t& hi, uint32_t& lo) {
    __nv_bfloat162 h = __floats2bfloat162_rn(x, y);
    float rx = x - __bfloat162float(h.x);
    float ry = y - __bfloat162float(h.y);
    __nv_bfloat162 l = __floats2bfloat162_rn(rx, ry);
    hi = *reinterpret_cast<uint32_t*>(&h);
    lo = *reinterpret_cast<uint32_t*>(&l);
}

__device__ __forceinline__ void cp16(uint32_t saddr, const void* g) {
    asm volatile("cp.async.cg.shared.global [%0], [%1], 16;"
                 :: "r"(saddr), "l"(g) : "memory");
}
__device__ __forceinline__ void cp_commit() {
    asm volatile("cp.async.commit_group;" ::: "memory");
}
template <int NN>
__device__ __forceinline__ void cp_wait() {
    asm volatile("cp.async.wait_group %0;" :: "n"(NN) : "memory");
}

/* ------------------------------------------------------------------ */
/* split kernel: fp32 -> bf16 hi/lo pair                               */
/* ------------------------------------------------------------------ */
__global__ void __launch_bounds__(256)
split_fp32(const float* __restrict__ src, __nv_bfloat16* __restrict__ h,
           __nv_bfloat16* __restrict__ l, int n4)
{
    int i      = blockIdx.x * blockDim.x + threadIdx.x;
    int stride = gridDim.x * blockDim.x;
    for (; i < n4; i += stride) {
        float4 v = reinterpret_cast<const float4*>(src)[i];
        uint32_t h0, l0, h1, l1;
        split2(v.x, v.y, h0, l0);
        split2(v.z, v.w, h1, l1);
        reinterpret_cast<uint2*>(h)[i] = make_uint2(h0, h1);
        reinterpret_cast<uint2*>(l)[i] = make_uint2(l0, l1);
    }
}

/* ------------------------------------------------------------------ */
/* HMMA GEMM on pre-split bf16: C = A * W^T.                           */
/* tile 128x128, BK=32, 256 thr (8 warps 4x2), 2 CTAs/SM.              */
/* 3-stage cp.async pipeline; swizzled pad-free smem (64B rows).       */
/* ------------------------------------------------------------------ */
#define ARR_B (128 * 64u)                      /* bytes per array (8 KB)  */
#define STAGE_B (4 * ARR_B)                    /* bytes per stage (32 KB) */
#define GEMM_SMEM (3 * STAGE_B)                /* 98304 B dynamic         */

template <int MODE>
__global__ void __launch_bounds__(256, 2)
gemm_bf16(const __nv_bfloat16* __restrict__ Ah, const __nv_bfloat16* __restrict__ Al,
          const __nv_bfloat16* __restrict__ Wh, const __nv_bfloat16* __restrict__ Wl,
          float* __restrict__ C, int K, int Nout)
{
    extern __shared__ __nv_bfloat16 smem[];
    const uint32_t sb = smem_u32(smem);

    const int tid  = threadIdx.x;
    const int lane = tid & 31;
    const int wid  = tid >> 5;
    const int wm   = wid & 3;
    const int wn   = wid >> 2;

    const int m0 = blockIdx.y * 128;
    const int j0 = blockIdx.x * 128;

    /* per-thread copy slots: rows tid>>2 and +64, 16B chunk q0 */
    const int row0 = tid >> 2;
    const int row1 = row0 + 64;
    const int q0   = tid & 3;
    const size_t gA0 = (size_t)(m0 + row0) * K + q0 * 8;
    const size_t gA1 = (size_t)(m0 + row1) * K + q0 * 8;
    const size_t gW0 = (size_t)(j0 + row0) * K + q0 * 8;
    const size_t gW1 = (size_t)(j0 + row1) * K + q0 * 8;
    const uint32_t sso0 = swz((uint32_t)(row0 * 64 + q0 * 16));
    const uint32_t sso1 = swz((uint32_t)(row1 * 64 + q0 * 16));

#define ISSUE_CHUNK(kc, stage)                                                \
    do {                                                                      \
        const int koff = (kc) * 32;                                          \
        const uint32_t st_ = sb + (uint32_t)(stage) * STAGE_B;               \
        cp16(st_ + 0 * ARR_B + sso0, Ah + gA0 + koff);                       \
        cp16(st_ + 0 * ARR_B + sso1, Ah + gA1 + koff);                       \
        cp16(st_ + 1 * ARR_B + sso0, Al + gA0 + koff);                       \
        cp16(st_ + 1 * ARR_B + sso1, Al + gA1 + koff);                       \
        cp16(st_ + 2 * ARR_B + sso0, Wh + gW0 + koff);                       \
        cp16(st_ + 2 * ARR_B + sso1, Wh + gW1 + koff);                       \
        cp16(st_ + 3 * ARR_B + sso0, Wl + gW0 + koff);                       \
        cp16(st_ + 3 * ARR_B + sso1, Wl + gW1 + koff);                       \
        cp_commit();                                                         \
    } while (0)

    /* fragment address components (tile-relative byte offsets, pre-swizzle) */
    const int arow = wm * 32 + (lane & 15);
    const int acolb = (lane >> 4) * 16;          /* 0 or 16 bytes */
    const int brow = wn * 64 + ((lane & 7) | ((lane & 16) >> 1));
    const int bcolb = (lane & 8) * 2;            /* 0 or 16 bytes */

    float acc[2][8][4];
#pragma unroll
    for (int i = 0; i < 2; i++)
#pragma unroll
        for (int j = 0; j < 8; j++)
#pragma unroll
            for (int c = 0; c < 4; c++) acc[i][j][c] = 0.f;

    const int nchunk = K >> 5;

    ISSUE_CHUNK(0, 0);
    ISSUE_CHUNK(1, 1);

    for (int kc = 0; kc < nchunk; kc++) {
        cp_wait<1>();          /* chunk kc complete; kc+1 may still fly */
        __syncthreads();       /* visibility + stage-reuse protection   */
        if (kc + 2 < nchunk) {
            int st = kc + 2;
            ISSUE_CHUNK(st, st - (st / 3) * 3);
        }

        const uint32_t stg = sb + (uint32_t)(kc - (kc / 3) * 3) * STAGE_B;
        const uint32_t sAh = stg;
        const uint32_t sAl = stg + 1 * ARR_B;
        const uint32_t sWh = stg + 2 * ARR_B;
        const uint32_t sWl = stg + 3 * ARR_B;

#pragma unroll
        for (int ks = 0; ks < 2; ks++) {
            uint32_t ah[2][4], al[2][4];
#pragma unroll
            for (int mt = 0; mt < 2; mt++) {
                uint32_t off = swz((uint32_t)((arow + mt * 16) * 64 + ks * 32 + acolb));
                ldsm4(sAh + off, ah[mt][0], ah[mt][1], ah[mt][2], ah[mt][3]);
                ldsm4(sAl + off, al[mt][0], al[mt][1], al[mt][2], al[mt][3]);
            }
#pragma unroll
            for (int np = 0; np < 4; np++) {
                uint32_t boff = swz((uint32_t)((brow + np * 16) * 64 + ks * 32 + bcolb));
                uint32_t bh[4], bl[4];
                ldsm4(sWh + boff, bh[0], bh[1], bh[2], bh[3]);
                ldsm4(sWl + boff, bl[0], bl[1], bl[2], bl[3]);
#pragma unroll
                for (int mt = 0; mt < 2; mt++) {
#pragma unroll
                    for (int sub = 0; sub < 2; sub++) {
                        float* c = acc[mt][np * 2 + sub];
                        mma16816(c, ah[mt][0], ah[mt][1], ah[mt][2], ah[mt][3],
                                 bh[sub * 2], bh[sub * 2 + 1]);
                        mma16816(c, ah[mt][0], ah[mt][1], ah[mt][2], ah[mt][3],
                                 bl[sub * 2], bl[sub * 2 + 1]);
                        mma16816(c, al[mt][0], al[mt][1], al[mt][2], al[mt][3],
                                 bh[sub * 2], bh[sub * 2 + 1]);
                    }
                }
            }
        }
    }

    /* epilogue */
    const int grp = lane >> 2;
    const int qid = lane & 3;
#pragma unroll
    for (int mt = 0; mt < 2; mt++) {
#pragma unroll
        for (int nt = 0; nt < 8; nt++) {
            const float* c = acc[mt][nt];
            int row = m0 + wm * 32 + mt * 16 + grp;
            int col = j0 + wn * 64 + nt * 8 + qid * 2;
#pragma unroll
            for (int half = 0; half < 2; half++) {
                int m = row + half * 8;
                float vx = c[half * 2], vy = c[half * 2 + 1];
                if (MODE == 0) {
                    int s  = col >> 10;
                    int rr = col & 1023;
                    int h  = rr >> 6;
                    int dh = rr & 63;
                    int b  = m >> 11;
                    int n  = m & 2047;
                    size_t idx = (((size_t)(b * H_ + h) * N_ + n) * DH_ + dh);
                    float sc = (s == 0) ? SCALE_ : 1.f;
                    uint32_t hi, lo;
                    split2(vx * sc, vy * sc, hi, lo);
                    __nv_bfloat16* bhp = (s == 0) ? g_qh : (s == 1) ? g_kh : g_vh;
                    __nv_bfloat16* blp = (s == 0) ? g_ql : (s == 1) ? g_kl : g_vl;
                    *reinterpret_cast<uint32_t*>(bhp + idx) = hi;
                    *reinterpret_cast<uint32_t*>(blp + idx) = lo;
                } else {
                    *reinterpret_cast<float2*>(C + (size_t)m * Nout + col) =
                        make_float2(vx, vy);
                }
            }
        }
    }
}

/* ------------------------------------------------------------------ */
/* Flash-attention (R8 version, unchanged). K/V double-buffered via    */
/* cp.async; V row-major, B-fragments via ldmatrix.trans. 2 CTAs/SM.   */
/* ------------------------------------------------------------------ */
#define ASTR 72
#define SM_QH 0
#define SM_QL (128 * ASTR)
#define SM_ST0 (2 * 128 * ASTR)
#define STG_E  (4 * 64 * ASTR)
#define OFF_KH 0
#define OFF_KL (64 * ASTR)
#define OFF_VH (2 * 64 * ASTR)
#define OFF_VL (3 * 64 * ASTR)
#define ATT_SMEM_ELEMS (SM_ST0 + 2 * STG_E)   /* 55296 bf16 = 110592 B */

__global__ void __launch_bounds__(256, 2)
attn_mma()
{
    extern __shared__ __nv_bfloat16 sbuf[];

    const int qt = (N_ / 128 - 1) - (blockIdx.x >> 5);  /* heavy tiles first */
    const int bh = blockIdx.x & 31;
    const int b  = bh >> 4;
    const int h  = bh & 15;

    const int tid  = threadIdx.x;
    const int lane = tid & 31;
    const int w    = tid >> 5;

    const __nv_bfloat16* Qbh = g_qh + (size_t)bh * N_ * DH_;
    const __nv_bfloat16* Qbl = g_ql + (size_t)bh * N_ * DH_;
    const __nv_bfloat16* Kbh = g_kh + (size_t)bh * N_ * DH_;
    const __nv_bfloat16* Kbl = g_kl + (size_t)bh * N_ * DH_;
    const __nv_bfloat16* Vbh = g_vh + (size_t)bh * N_ * DH_;
    const __nv_bfloat16* Vbl = g_vl + (size_t)bh * N_ * DH_;

    const uint32_t sB = smem_u32(sbuf);

    const int kr0 = tid >> 3;
    const int kr1 = (tid + 256) >> 3;
    const int kc8 = (tid & 7) * 8;
    const uint32_t kso0 = (uint32_t)(kr0 * ASTR + kc8) * 2;
    const uint32_t kso1 = (uint32_t)(kr1 * ASTR + kc8) * 2;

#define ISSUE_KV(jt, stage)                                                   \
    do {                                                                      \
        const size_t g0 = (size_t)((jt) * 64 + kr0) * DH_ + kc8;             \
        const size_t g1 = (size_t)((jt) * 64 + kr1) * DH_ + kc8;             \
        const uint32_t st_ = sB + (SM_ST0 + (stage) * STG_E) * 2;            \
        cp16(st_ + OFF_KH * 2 + kso0, Kbh + g0);                             \
        cp16(st_ + OFF_KH * 2 + kso1, Kbh + g1);                             \
        cp16(st_ + OFF_KL * 2 + kso0, Kbl + g0);                             \
        cp16(st_ + OFF_KL * 2 + kso1, Kbl + g1);                             \
        cp16(st_ + OFF_VH * 2 + kso0, Vbh + g0);                             \
        cp16(st_ + OFF_VH * 2 + kso1, Vbh + g1);                             \
        cp16(st_ + OFF_VL * 2 + kso0, Vbl + g0);                             \
        cp16(st_ + OFF_VL * 2 + kso1, Vbl + g1);                             \
        cp_commit();                                                         \
    } while (0)

    ISSUE_KV(0, 0);

    /* ---- load Q tile (pre-scaled, pre-split) ---- */
#pragma unroll
    for (int it = 0; it < 4; it++) {
        int idx = tid + it * 256;
        int r   = idx >> 3;
        int c8  = (idx & 7) * 8;
        size_t g = (size_t)(qt * 128 + r) * DH_ + c8;
        *reinterpret_cast<uint4*>(sbuf + SM_QH + r * ASTR + c8) =
            *reinterpret_cast<const uint4*>(Qbh + g);
        *reinterpret_cast<uint4*>(sbuf + SM_QL + r * ASTR + c8) =
            *reinterpret_cast<const uint4*>(Qbl + g);
    }
    __syncthreads();

    /* ---- Q fragments into registers ---- */
    uint32_t qh[4][4], ql[4][4];
    {
        const uint32_t a0 = sB +
            2u * ((uint32_t)((w * 16 + (lane & 15)) * ASTR) + ((lane >> 4) << 3));
#pragma unroll
        for (int ks = 0; ks < 4; ks++) {
            ldsm4(a0 + SM_QH * 2 + 2u * (ks * 16),
                  qh[ks][0], qh[ks][1], qh[ks][2], qh[ks][3]);
            ldsm4(a0 + SM_QL * 2 + 2u * (ks * 16),
                  ql[ks][0], ql[ks][1], ql[ks][2], ql[ks][3]);
        }
    }

    const uint32_t bpat = 2u * ((uint32_t)(((lane & 7) | ((lane & 16) >> 1)) * ASTR)
                                + (lane & 8));
    const uint32_t vpat = 2u * ((uint32_t)((lane & 15) * ASTR) + ((lane & 16) >> 1));

    float o[8][4];
#pragma unroll
    for (int i = 0; i < 8; i++)
#pragma unroll
        for (int c = 0; c < 4; c++) o[i][c] = 0.f;
    float mrow0 = -INFINITY, mrow1 = -INFINITY;
    float lrow0 = 0.f, lrow1 = 0.f;

    const int qglo   = qt * 128 + w * 16;
    const int ntiles = 2 * qt + 2;

    for (int jt = 0; jt < ntiles; jt++) {
        cp_wait<0>();
        __syncthreads();
        if (jt + 1 < ntiles) ISSUE_KV(jt + 1, (jt + 1) & 1);

        if (jt * 64 > qglo + 15) continue;

        const uint32_t stg = sB + (SM_ST0 + (jt & 1) * STG_E) * 2;
        const uint32_t sKH = stg + OFF_KH * 2;
        const uint32_t sKL = stg + OFF_KL * 2;
        const uint32_t sVH = stg + OFF_VH * 2;
        const uint32_t sVL = stg + OFF_VL * 2;

        /* ---- S = Q K^T ---- */
        float s[8][4];
#pragma unroll
        for (int i = 0; i < 8; i++)
#pragma unroll
            for (int c = 0; c < 4; c++) s[i][c] = 0.f;

#pragma unroll
        for (int ks = 0; ks < 4; ks++) {
#pragma unroll
            for (int np = 0; np < 4; np++) {
                const uint32_t boff = bpat + 2u * (np * 16 * ASTR + ks * 16);
                uint32_t bh4[4], bl4[4];
                ldsm4(sKH + boff, bh4[0], bh4[1], bh4[2], bh4[3]);
                ldsm4(sKL + boff, bl4[0], bl4[1], bl4[2], bl4[3]);
#pragma unroll
                for (int sub = 0; sub < 2; sub++) {
                    float* c = s[np * 2 + sub];
                    mma16816(c, qh[ks][0], qh[ks][1], qh[ks][2], qh[ks][3],
                             bh4[sub * 2], bh4[sub * 2 + 1]);
                    mma16816(c, qh[ks][0], qh[ks][1], qh[ks][2], qh[ks][3],
                             bl4[sub * 2], bl4[sub * 2 + 1]);
                    mma16816(c, ql[ks][0], ql[ks][1], ql[ks][2], ql[ks][3],
                             bh4[sub * 2], bh4[sub * 2 + 1]);
                }
            }
        }

        /* ---- causal mask ---- */
        const int r0 = qglo + (lane >> 2);
        const int r1 = r0 + 8;
        if (jt * 64 + 63 > qglo) {
            const int colb = jt * 64 + (lane & 3) * 2;
#pragma unroll
            for (int nt = 0; nt < 8; nt++) {
                int c0 = colb + nt * 8;
                if (c0 > r0)     s[nt][0] = -INFINITY;
                if (c0 + 1 > r0) s[nt][1] = -INFINITY;
                if (c0 > r1)     s[nt][2] = -INFINITY;
                if (c0 + 1 > r1) s[nt][3] = -INFINITY;
            }
        }

        /* ---- online softmax ---- */
        float mt0 = s[0][0], mt1 = s[0][2];
#pragma unroll
        for (int nt = 0; nt < 8; nt++) {
            mt0 = fmaxf(mt0, fmaxf(s[nt][0], s[nt][1]));
            mt1 = fmaxf(mt1, fmaxf(s[nt][2], s[nt][3]));
        }
        mt0 = fmaxf(mt0, __shfl_xor_sync(0xffffffffu, mt0, 1));
        mt0 = fmaxf(mt0, __shfl_xor_sync(0xffffffffu, mt0, 2));
        mt1 = fmaxf(mt1, __shfl_xor_sync(0xffffffffu, mt1, 1));
        mt1 = fmaxf(mt1, __shfl_xor_sync(0xffffffffu, mt1, 2));

        const float mn0 = fmaxf(mrow0, mt0);
        const float mn1 = fmaxf(mrow1, mt1);
        const float al0 = __expf(mrow0 - mn0);
        const float al1 = __expf(mrow1 - mn1);

        float ps0 = 0.f, ps1 = 0.f;
#pragma unroll
        for (int nt = 0; nt < 8; nt++) {
            s[nt][0] = __expf(s[nt][0] - mn0);
            s[nt][1] = __expf(s[nt][1] - mn0);
            s[nt][2] = __expf(s[nt][2] - mn1);
            s[nt][3] = __expf(s[nt][3] - mn1);
            ps0 += s[nt][0] + s[nt][1];
            ps1 += s[nt][2] + s[nt][3];
        }
        ps0 += __shfl_xor_sync(0xffffffffu, ps0, 1);
        ps0 += __shfl_xor_sync(0xffffffffu, ps0, 2);
        ps1 += __shfl_xor_sync(0xffffffffu, ps1, 1);
        ps1 += __shfl_xor_sync(0xffffffffu, ps1, 2);

        lrow0 = lrow0 * al0 + ps0;
        lrow1 = lrow1 * al1 + ps1;
#pragma unroll
        for (int nt = 0; nt < 8; nt++) {
            o[nt][0] *= al0; o[nt][1] *= al0;
            o[nt][2] *= al1; o[nt][3] *= al1;
        }
        mrow0 = mn0;
        mrow1 = mn1;

        /* ---- O += P V (V fragments via ldmatrix.trans) ---- */
#pragma unroll
        for (int ks = 0; ks < 4; ks++) {
            uint32_t ph[4], pl[4];
            split2(s[2 * ks][0],     s[2 * ks][1],     ph[0], pl[0]);
            split2(s[2 * ks][2],     s[2 * ks][3],     ph[1], pl[1]);
            split2(s[2 * ks + 1][0], s[2 * ks + 1][1], ph[2], pl[2]);
            split2(s[2 * ks + 1][2], s[2 * ks + 1][3], ph[3], pl[3]);
#pragma unroll
            for (int np = 0; np < 4; np++) {
                const uint32_t voff = vpat + 2u * (ks * 16 * ASTR + np * 16);
                uint32_t bh4[4], bl4[4];
                ldsm4t(sVH + voff, bh4[0], bh4[1], bh4[2], bh4[3]);
                ldsm4t(sVL + voff, bl4[0], bl4[1], bl4[2], bl4[3]);
#pragma unroll
                for (int sub = 0; sub < 2; sub++) {
                    float* c = o[np * 2 + sub];
                    mma16816(c, ph[0], ph[1], ph[2], ph[3],
                             bh4[sub * 2], bh4[sub * 2 + 1]);
                    mma16816(c, ph[0], ph[1], ph[2], ph[3],
                             bl4[sub * 2], bl4[sub * 2 + 1]);
                    mma16816(c, pl[0], pl[1], pl[2], pl[3],
                             bh4[sub * 2], bh4[sub * 2 + 1]);
                }
            }
        }
    }

    /* ---- epilogue ---- */
    const float i0 = 1.f / lrow0;
    const float i1 = 1.f / lrow1;
    const int r0 = qt * 128 + w * 16 + (lane >> 2);
    const size_t base0 = ((size_t)b * N_ + r0) * D_ + h * DH_ + (lane & 3) * 2;
    const size_t base1 = base0 + 8 * D_;
#pragma unroll
    for (int nt = 0; nt < 8; nt++) {
        uint32_t hi, lo;
        split2(o[nt][0] * i0, o[nt][1] * i0, hi, lo);
        *reinterpret_cast<uint32_t*>(g_aoh + base0 + nt * 8) = hi;
        *reinterpret_cast<uint32_t*>(g_aol + base0 + nt * 8) = lo;
        split2(o[nt][2] * i1, o[nt][3] * i1, hi, lo);
        *reinterpret_cast<uint32_t*>(g_aoh + base1 + nt * 8) = hi;
        *reinterpret_cast<uint32_t*>(g_aol + base1 + nt * 8) = lo;
    }
}

/* ------------------------------------------------------------------ */
extern "C" void kernel_launch(void* const* d_in, const int* in_sizes, int n_in,
                              void* d_out, int out_size)
{
    const float* x    = (const float*)d_in[0];
    /* d_in[1] = mask (static causal structure, unused) */
    const float* Wqkv = (const float*)d_in[2];
    const float* Wout = (const float*)d_in[3];
    float* out = (float*)d_out;

    __nv_bfloat16 *xh, *xl, *wqh, *wql, *woh, *wol, *aoh, *aol;
    cudaGetSymbolAddress((void**)&xh,  g_xh);
    cudaGetSymbolAddress((void**)&xl,  g_xl);
    cudaGetSymbolAddress((void**)&wqh, g_wqh);
    cudaGetSymbolAddress((void**)&wql, g_wql);
    cudaGetSymbolAddress((void**)&woh, g_woh);
    cudaGetSymbolAddress((void**)&wol, g_wol);
    cudaGetSymbolAddress((void**)&aoh, g_aoh);
    cudaGetSymbolAddress((void**)&aol, g_aol);

    /* 0. split inputs to bf16 hi/lo */
    split_fp32<<<1024, 256>>>(x,    xh,  xl,  4096 * 1024 / 4);
    split_fp32<<<1024, 256>>>(Wqkv, wqh, wql, 3072 * 1024 / 4);
    split_fp32<<<512,  256>>>(Wout, woh, wol, 1024 * 1024 / 4);

    cudaFuncSetAttribute(gemm_bf16<0>,
                         cudaFuncAttributeMaxDynamicSharedMemorySize, GEMM_SMEM);
    cudaFuncSetAttribute(gemm_bf16<1>,
                         cudaFuncAttributeMaxDynamicSharedMemorySize, GEMM_SMEM);

    /* 1. QKV projection -> q/k/v hi/lo (q pre-scaled) */
    gemm_bf16<0><<<dim3(3072 / 128, 4096 / 128), 256, GEMM_SMEM>>>(
        xh, xl, wqh, wql, nullptr, D_, 3 * D_);

    /* 2. causal flash attention -> ao hi/lo */
    const int ATT_SMEM = ATT_SMEM_ELEMS * (int)sizeof(__nv_bfloat16);  /* 110592 */
    cudaFuncSetAttribute(attn_mma,
                         cudaFuncAttributeMaxDynamicSharedMemorySize, ATT_SMEM);
    attn_mma<<<dim3((N_ / 128) * 32), 256, ATT_SMEM>>>();

    /* 3. output projection -> d_out (fp32) */
    gemm_bf16<1><<<dim3(1024 / 128, 4096 / 128), 256, GEMM_SMEM>>>(
        aoh, aol, woh, wol, out, D_, D_);
}

// round 10
// speedup vs baseline: 2.3917x; 1.1809x over previous
#include <cuda_runtime.h>
#include <cuda_bf16.h>
#include <math.h>
#include <stdint.h>

#define B_ 2
#define N_ 2048
#define D_ 1024
#define H_ 16
#define DH_ 64
#define SCALE_ 0.125f   /* 64^-0.5, exact power of two */

/* ------------------------------------------------------------------ */
/* device scratch                                                      */
/* ------------------------------------------------------------------ */
__device__ __nv_bfloat16 g_qh[B_*H_*N_*DH_], g_ql[B_*H_*N_*DH_];
__device__ __nv_bfloat16 g_kh[B_*H_*N_*DH_], g_kl[B_*H_*N_*DH_];
__device__ __nv_bfloat16 g_vh[B_*H_*N_*DH_], g_vl[B_*H_*N_*DH_];
__device__ float         g_ao[B_*N_*D_];

/* ------------------------------------------------------------------ */
/* helpers                                                             */
/* ------------------------------------------------------------------ */
__device__ __forceinline__ uint32_t smem_u32(const void* p) {
    uint32_t a;
    asm("{ .reg .u64 t; cvta.to.shared.u64 t, %1; cvt.u32.u64 %0, t; }"
        : "=r"(a) : "l"(p));
    return a;
}

/* swizzle for 128B-row fp32 tiles: chunk' = chunk ^ (row & 7) */
__device__ __forceinline__ uint32_t swzA(uint32_t o) {
    return o ^ (((o >> 7) & 7u) << 4);
}

__device__ __forceinline__ void ldsm4(uint32_t addr, uint32_t& r0, uint32_t& r1,
                                      uint32_t& r2, uint32_t& r3) {
    asm volatile("ldmatrix.sync.aligned.m8n8.x4.shared.b16 {%0,%1,%2,%3}, [%4];"
                 : "=r"(r0), "=r"(r1), "=r"(r2), "=r"(r3) : "r"(addr));
}

__device__ __forceinline__ void ldsm4t(uint32_t addr, uint32_t& r0, uint32_t& r1,
                                       uint32_t& r2, uint32_t& r3) {
    asm volatile("ldmatrix.sync.aligned.m8n8.x4.trans.shared.b16 {%0,%1,%2,%3}, [%4];"
                 : "=r"(r0), "=r"(r1), "=r"(r2), "=r"(r3) : "r"(addr));
}

__device__ __forceinline__ void mma16816(float* c,
                                         uint32_t a0, uint32_t a1, uint32_t a2, uint32_t a3,
                                         uint32_t b0, uint32_t b1) {
    asm volatile(
        "mma.sync.aligned.m16n8k16.row.col.f32.bf16.bf16.f32 "
        "{%0,%1,%2,%3}, {%4,%5,%6,%7}, {%8,%9}, {%0,%1,%2,%3};"
        : "+f"(c[0]), "+f"(c[1]), "+f"(c[2]), "+f"(c[3])
        : "r"(a0), "r"(a1), "r"(a2), "r"(a3), "r"(b0), "r"(b1));
}

__device__ __forceinline__ void mma_tf32(float* c,
                                         uint32_t a0, uint32_t a1, uint32_t a2, uint32_t a3,
                                         uint32_t b0, uint32_t b1) {
    asm volatile(
        "mma.sync.aligned.m16n8k8.row.col.f32.tf32.tf32.f32 "
        "{%0,%1,%2,%3}, {%4,%5,%6,%7}, {%8,%9}, {%0,%1,%2,%3};"
        : "+f"(c[0]), "+f"(c[1]), "+f"(c[2]), "+f"(c[3])
        : "r"(a0), "r"(a1), "r"(a2), "r"(a3), "r"(b0), "r"(b1));
}

__device__ __forceinline__ uint32_t f2tf(uint32_t bits) {
    uint32_t r;
    asm("cvt.rna.tf32.f32 %0, %1;" : "=r"(r) : "f"(__uint_as_float(bits)));
    return r;
}

__device__ __forceinline__ void split2(float x, float y, uint32_t& hi, uint32_t& lo) {
    __nv_bfloat162 h = __floats2bfloat162_rn(x, y);
    float rx = x - __bfloat162float(h.x);
    float ry = y - __bfloat162float(h.y);
    __nv_bfloat162 l = __floats2bfloat162_rn(rx, ry);
    hi = *reinterpret_cast<uint32_t*>(&h);
    lo = *reinterpret_cast<uint32_t*>(&l);
}

__device__ __forceinline__ void cp16(uint32_t saddr, const void* g) {
    asm volatile("cp.async.cg.shared.global [%0], [%1], 16;"
                 :: "r"(saddr), "l"(g) : "memory");
}
__device__ __forceinline__ void cp_commit() {
    asm volatile("cp.async.commit_group;" ::: "memory");
}
template <int NN>
__device__ __forceinline__ void cp_wait() {
    asm volatile("cp.async.wait_group %0;" :: "n"(NN) : "memory");
}

/* ------------------------------------------------------------------ */
/* TF32 HMMA GEMM on raw fp32: C = A * W^T.                            */
/* tile 128x128, BK=32, 256 thr (8 warps 4x2), 2 CTAs/SM.              */
/* 3-stage cp.async pipeline; swizzled pad-free smem (128B rows).      */
/* Fragments via ldmatrix.b16 reinterpretation + cvt.rna.tf32.         */
/* MODE 0: epilogue -> q/k/v bf16 hi/lo (q scaled). MODE 1: fp32 C.    */
/* ------------------------------------------------------------------ */
#define GARR_B (128 * 128u)                 /* bytes per fp32 array (16 KB) */
#define GSTAGE_B (2 * GARR_B)               /* bytes per stage (32 KB)      */
#define GEMM_SMEM (3 * GSTAGE_B)            /* 98304 B dynamic              */

template <int MODE>
__global__ void __launch_bounds__(256, 2)
gemm_tf32(const float* __restrict__ A, const float* __restrict__ W,
          float* __restrict__ C, int K, int Nout)
{
    extern __shared__ float smem[];
    const uint32_t sb = smem_u32(smem);

    const int tid  = threadIdx.x;
    const int lane = tid & 31;
    const int wid  = tid >> 5;
    const int wm   = wid & 3;
    const int wn   = wid >> 2;

    const int m0 = blockIdx.y * 128;
    const int j0 = blockIdx.x * 128;

    /* copy slots: idx = tid + i*256 (i<4): row = idx>>3, chunk q = idx&7 */
    const int q0 = tid & 7;

#define ISSUE_CHUNK(kc, stage)                                                \
    do {                                                                      \
        const int koff = (kc) * 32;                                          \
        const uint32_t st_ = sb + (uint32_t)(stage) * GSTAGE_B;              \
        _Pragma("unroll")                                                     \
        for (int i_ = 0; i_ < 4; i_++) {                                     \
            int r_ = (tid + i_ * 256) >> 3;                                  \
            uint32_t so_ = swzA((uint32_t)(r_ * 128 + q0 * 16));             \
            cp16(st_ + so_,          A + (size_t)(m0 + r_) * K + koff + q0 * 4); \
            cp16(st_ + GARR_B + so_, W + (size_t)(j0 + r_) * K + koff + q0 * 4); \
        }                                                                     \
        cp_commit();                                                         \
    } while (0)

    /* ldsm lane address components */
    const int a_r8 = lane & 7;
    const int a_rh = (lane >> 3) & 1;     /* A: row +8 for tiles 1,3   */
    const int a_ch = lane >> 4;           /* A: chunk +1 for tiles 2,3 */
    const int b_rh = lane >> 4;           /* B: row +8 for tiles 2,3   */
    const int b_ch = (lane >> 3) & 1;     /* B: chunk +1 for tiles 1,3 */

    float acc[2][8][4];
#pragma unroll
    for (int i = 0; i < 2; i++)
#pragma unroll
        for (int j = 0; j < 8; j++)
#pragma unroll
            for (int c = 0; c < 4; c++) acc[i][j][c] = 0.f;

    const int nchunk = K >> 5;

    ISSUE_CHUNK(0, 0);
    ISSUE_CHUNK(1, 1);

    for (int kc = 0; kc < nchunk; kc++) {
        cp_wait<1>();
        __syncthreads();
        if (kc + 2 < nchunk) {
            int st = kc + 2;
            ISSUE_CHUNK(st, st - (st / 3) * 3);
        }

        const uint32_t stg = sb + (uint32_t)(kc - (kc / 3) * 3) * GSTAGE_B;
        const uint32_t sA  = stg;
        const uint32_t sW  = stg + GARR_B;

#pragma unroll
        for (int ks = 0; ks < 4; ks++) {       /* k8 steps within BK=32 */
            /* A fragments: per mt one ldsm4 (m16 x k8), then cvt */
            uint32_t a[2][4];
#pragma unroll
            for (int mt = 0; mt < 2; mt++) {
                int row   = wm * 32 + mt * 16 + a_r8 + a_rh * 8;
                int chunk = ks * 2 + a_ch;
                uint32_t addr = sA + swzA((uint32_t)(row * 128 + chunk * 16));
                ldsm4(addr, a[mt][0], a[mt][1], a[mt][2], a[mt][3]);
#pragma unroll
                for (int e = 0; e < 4; e++) a[mt][e] = f2tf(a[mt][e]);
            }
            /* B fragments: per npair (2 n-blocks) one ldsm4 */
#pragma unroll
            for (int np = 0; np < 4; np++) {
                int row   = wn * 64 + np * 16 + a_r8 + b_rh * 8;
                int chunk = ks * 2 + b_ch;
                uint32_t addr = sW + swzA((uint32_t)(row * 128 + chunk * 16));
                uint32_t bfr[4];
                ldsm4(addr, bfr[0], bfr[1], bfr[2], bfr[3]);
#pragma unroll
                for (int e = 0; e < 4; e++) bfr[e] = f2tf(bfr[e]);
#pragma unroll
                for (int mt = 0; mt < 2; mt++) {
                    mma_tf32(acc[mt][np * 2 + 0], a[mt][0], a[mt][1], a[mt][2], a[mt][3],
                             bfr[0], bfr[1]);
                    mma_tf32(acc[mt][np * 2 + 1], a[mt][0], a[mt][1], a[mt][2], a[mt][3],
                             bfr[2], bfr[3]);
                }
            }
        }
    }

    /* epilogue */
    const int grp = lane >> 2;
    const int qid = lane & 3;
#pragma unroll
    for (int mt = 0; mt < 2; mt++) {
#pragma unroll
        for (int nt = 0; nt < 8; nt++) {
            const float* c = acc[mt][nt];
            int row = m0 + wm * 32 + mt * 16 + grp;
            int col = j0 + wn * 64 + nt * 8 + qid * 2;
#pragma unroll
            for (int half = 0; half < 2; half++) {
                int m = row + half * 8;
                float vx = c[half * 2], vy = c[half * 2 + 1];
                if (MODE == 0) {
                    int s  = col >> 10;
                    int rr = col & 1023;
                    int h  = rr >> 6;
                    int dh = rr & 63;
                    int b  = m >> 11;
                    int n  = m & 2047;
                    size_t idx = (((size_t)(b * H_ + h) * N_ + n) * DH_ + dh);
                    float sc = (s == 0) ? SCALE_ : 1.f;
                    uint32_t hi, lo;
                    split2(vx * sc, vy * sc, hi, lo);
                    __nv_bfloat16* bhp = (s == 0) ? g_qh : (s == 1) ? g_kh : g_vh;
                    __nv_bfloat16* blp = (s == 0) ? g_ql : (s == 1) ? g_kl : g_vl;
                    *reinterpret_cast<uint32_t*>(bhp + idx) = hi;
                    *reinterpret_cast<uint32_t*>(blp + idx) = lo;
                } else {
                    *reinterpret_cast<float2*>(C + (size_t)m * Nout + col) =
                        make_float2(vx, vy);
                }
            }
        }
    }
}

/* ------------------------------------------------------------------ */
/* Flash-attention (bf16 hi/lo, unchanged math). K/V double-buffered   */
/* via cp.async; V B-fragments via ldmatrix.trans. 2 CTAs/SM.          */
/* Epilogue now writes fp32 g_ao directly.                             */
/* ------------------------------------------------------------------ */
#define ASTR 72
#define SM_QH 0
#define SM_QL (128 * ASTR)
#define SM_ST0 (2 * 128 * ASTR)
#define STG_E  (4 * 64 * ASTR)
#define OFF_KH 0
#define OFF_KL (64 * ASTR)
#define OFF_VH (2 * 64 * ASTR)
#define OFF_VL (3 * 64 * ASTR)
#define ATT_SMEM_ELEMS (SM_ST0 + 2 * STG_E)   /* 55296 bf16 = 110592 B */

__global__ void __launch_bounds__(256, 2)
attn_mma()
{
    extern __shared__ __nv_bfloat16 sbuf[];

    const int qt = (N_ / 128 - 1) - (blockIdx.x >> 5);  /* heavy tiles first */
    const int bh = blockIdx.x & 31;
    const int b  = bh >> 4;
    const int h  = bh & 15;

    const int tid  = threadIdx.x;
    const int lane = tid & 31;
    const int w    = tid >> 5;

    const __nv_bfloat16* Qbh = g_qh + (size_t)bh * N_ * DH_;
    const __nv_bfloat16* Qbl = g_ql + (size_t)bh * N_ * DH_;
    const __nv_bfloat16* Kbh = g_kh + (size_t)bh * N_ * DH_;
    const __nv_bfloat16* Kbl = g_kl + (size_t)bh * N_ * DH_;
    const __nv_bfloat16* Vbh = g_vh + (size_t)bh * N_ * DH_;
    const __nv_bfloat16* Vbl = g_vl + (size_t)bh * N_ * DH_;

    const uint32_t sB = smem_u32(sbuf);

    const int kr0 = tid >> 3;
    const int kr1 = (tid + 256) >> 3;
    const int kc8 = (tid & 7) * 8;
    const uint32_t kso0 = (uint32_t)(kr0 * ASTR + kc8) * 2;
    const uint32_t kso1 = (uint32_t)(kr1 * ASTR + kc8) * 2;

#define ISSUE_KV(jt, stage)                                                   \
    do {                                                                      \
        const size_t g0 = (size_t)((jt) * 64 + kr0) * DH_ + kc8;             \
        const size_t g1 = (size_t)((jt) * 64 + kr1) * DH_ + kc8;             \
        const uint32_t st_ = sB + (SM_ST0 + (stage) * STG_E) * 2;            \
        cp16(st_ + OFF_KH * 2 + kso0, Kbh + g0);                             \
        cp16(st_ + OFF_KH * 2 + kso1, Kbh + g1);                             \
        cp16(st_ + OFF_KL * 2 + kso0, Kbl + g0);                             \
        cp16(st_ + OFF_KL * 2 + kso1, Kbl + g1);                             \
        cp16(st_ + OFF_VH * 2 + kso0, Vbh + g0);                             \
        cp16(st_ + OFF_VH * 2 + kso1, Vbh + g1);                             \
        cp16(st_ + OFF_VL * 2 + kso0, Vbl + g0);                             \
        cp16(st_ + OFF_VL * 2 + kso1, Vbl + g1);                             \
        cp_commit();                                                         \
    } while (0)

    ISSUE_KV(0, 0);

    /* ---- load Q tile (pre-scaled, pre-split) ---- */
#pragma unroll
    for (int it = 0; it < 4; it++) {
        int idx = tid + it * 256;
        int r   = idx >> 3;
        int c8  = (idx & 7) * 8;
        size_t g = (size_t)(qt * 128 + r) * DH_ + c8;
        *reinterpret_cast<uint4*>(sbuf + SM_QH + r * ASTR + c8) =
            *reinterpret_cast<const uint4*>(Qbh + g);
        *reinterpret_cast<uint4*>(sbuf + SM_QL + r * ASTR + c8) =
            *reinterpret_cast<const uint4*>(Qbl + g);
    }
    __syncthreads();

    /* ---- Q fragments into registers ---- */
    uint32_t qh[4][4], ql[4][4];
    {
        const uint32_t a0 = sB +
            2u * ((uint32_t)((w * 16 + (lane & 15)) * ASTR) + ((lane >> 4) << 3));
#pragma unroll
        for (int ks = 0; ks < 4; ks++) {
            ldsm4(a0 + SM_QH * 2 + 2u * (ks * 16),
                  qh[ks][0], qh[ks][1], qh[ks][2], qh[ks][3]);
            ldsm4(a0 + SM_QL * 2 + 2u * (ks * 16),
                  ql[ks][0], ql[ks][1], ql[ks][2], ql[ks][3]);
        }
    }

    const uint32_t bpat = 2u * ((uint32_t)(((lane & 7) | ((lane & 16) >> 1)) * ASTR)
                                + (lane & 8));
    const uint32_t vpat = 2u * ((uint32_t)((lane & 15) * ASTR) + ((lane & 16) >> 1));

    float o[8][4];
#pragma unroll
    for (int i = 0; i < 8; i++)
#pragma unroll
        for (int c = 0; c < 4; c++) o[i][c] = 0.f;
    float mrow0 = -INFINITY, mrow1 = -INFINITY;
    float lrow0 = 0.f, lrow1 = 0.f;

    const int qglo   = qt * 128 + w * 16;
    const int ntiles = 2 * qt + 2;

    for (int jt = 0; jt < ntiles; jt++) {
        cp_wait<0>();
        __syncthreads();
        if (jt + 1 < ntiles) ISSUE_KV(jt + 1, (jt + 1) & 1);

        if (jt * 64 > qglo + 15) continue;

        const uint32_t stg = sB + (SM_ST0 + (jt & 1) * STG_E) * 2;
        const uint32_t sKH = stg + OFF_KH * 2;
        const uint32_t sKL = stg + OFF_KL * 2;
        const uint32_t sVH = stg + OFF_VH * 2;
        const uint32_t sVL = stg + OFF_VL * 2;

        /* ---- S = Q K^T ---- */
        float s[8][4];
#pragma unroll
        for (int i = 0; i < 8; i++)
#pragma unroll
            for (int c = 0; c < 4; c++) s[i][c] = 0.f;

#pragma unroll
        for (int ks = 0; ks < 4; ks++) {
#pragma unroll
            for (int np = 0; np < 4; np++) {
                const uint32_t boff = bpat + 2u * (np * 16 * ASTR + ks * 16);
                uint32_t bh4[4], bl4[4];
                ldsm4(sKH + boff, bh4[0], bh4[1], bh4[2], bh4[3]);
                ldsm4(sKL + boff, bl4[0], bl4[1], bl4[2], bl4[3]);
#pragma unroll
                for (int sub = 0; sub < 2; sub++) {
                    float* c = s[np * 2 + sub];
                    mma16816(c, qh[ks][0], qh[ks][1], qh[ks][2], qh[ks][3],
                             bh4[sub * 2], bh4[sub * 2 + 1]);
                    mma16816(c, qh[ks][0], qh[ks][1], qh[ks][2], qh[ks][3],
                             bl4[sub * 2], bl4[sub * 2 + 1]);
                    mma16816(c, ql[ks][0], ql[ks][1], ql[ks][2], ql[ks][3],
                             bh4[sub * 2], bh4[sub * 2 + 1]);
                }
            }
        }

        /* ---- causal mask ---- */
        const int r0 = qglo + (lane >> 2);
        const int r1 = r0 + 8;
        if (jt * 64 + 63 > qglo) {
            const int colb = jt * 64 + (lane & 3) * 2;
#pragma unroll
            for (int nt = 0; nt < 8; nt++) {
                int c0 = colb + nt * 8;
                if (c0 > r0)     s[nt][0] = -INFINITY;
                if (c0 + 1 > r0) s[nt][1] = -INFINITY;
                if (c0 > r1)     s[nt][2] = -INFINITY;
                if (c0 + 1 > r1) s[nt][3] = -INFINITY;
            }
        }

        /* ---- online softmax ---- */
        float mt0 = s[0][0], mt1 = s[0][2];
#pragma unroll
        for (int nt = 0; nt < 8; nt++) {
            mt0 = fmaxf(mt0, fmaxf(s[nt][0], s[nt][1]));
            mt1 = fmaxf(mt1, fmaxf(s[nt][2], s[nt][3]));
        }
        mt0 = fmaxf(mt0, __shfl_xor_sync(0xffffffffu, mt0, 1));
        mt0 = fmaxf(mt0, __shfl_xor_sync(0xffffffffu, mt0, 2));
        mt1 = fmaxf(mt1, __shfl_xor_sync(0xffffffffu, mt1, 1));
        mt1 = fmaxf(mt1, __shfl_xor_sync(0xffffffffu, mt1, 2));

        const float mn0 = fmaxf(mrow0, mt0);
        const float mn1 = fmaxf(mrow1, mt1);
        const float al0 = __expf(mrow0 - mn0);
        const float al1 = __expf(mrow1 - mn1);

        float ps0 = 0.f, ps1 = 0.f;
#pragma unroll
        for (int nt = 0; nt < 8; nt++) {
            s[nt][0] = __expf(s[nt][0] - mn0);
            s[nt][1] = __expf(s[nt][1] - mn0);
            s[nt][2] = __expf(s[nt][2] - mn1);
            s[nt][3] = __expf(s[nt][3] - mn1);
            ps0 += s[nt][0] + s[nt][1];
            ps1 += s[nt][2] + s[nt][3];
        }
        ps0 += __shfl_xor_sync(0xffffffffu, ps0, 1);
        ps0 += __shfl_xor_sync(0xffffffffu, ps0, 2);
        ps1 += __shfl_xor_sync(0xffffffffu, ps1, 1);
        ps1 += __shfl_xor_sync(0xffffffffu, ps1, 2);

        lrow0 = lrow0 * al0 + ps0;
        lrow1 = lrow1 * al1 + ps1;
#pragma unroll
        for (int nt = 0; nt < 8; nt++) {
            o[nt][0] *= al0; o[nt][1] *= al0;
            o[nt][2] *= al1; o[nt][3] *= al1;
        }
        mrow0 = mn0;
        mrow1 = mn1;

        /* ---- O += P V (V fragments via ldmatrix.trans) ---- */
#pragma unroll
        for (int ks = 0; ks < 4; ks++) {
            uint32_t ph[4], pl[4];
            split2(s[2 * ks][0],     s[2 * ks][1],     ph[0], pl[0]);
            split2(s[2 * ks][2],     s[2 * ks][3],     ph[1], pl[1]);
            split2(s[2 * ks + 1][0], s[2 * ks + 1][1], ph[2], pl[2]);
            split2(s[2 * ks + 1][2], s[2 * ks + 1][3], ph[3], pl[3]);
#pragma unroll
            for (int np = 0; np < 4; np++) {
                const uint32_t voff = vpat + 2u * (ks * 16 * ASTR + np * 16);
                uint32_t bh4[4], bl4[4];
                ldsm4t(sVH + voff, bh4[0], bh4[1], bh4[2], bh4[3]);
                ldsm4t(sVL + voff, bl4[0], bl4[1], bl4[2], bl4[3]);
#pragma unroll
                for (int sub = 0; sub < 2; sub++) {
                    float* c = o[np * 2 + sub];
                    mma16816(c, ph[0], ph[1], ph[2], ph[3],
                             bh4[sub * 2], bh4[sub * 2 + 1]);
                    mma16816(c, ph[0], ph[1], ph[2], ph[3],
                             bl4[sub * 2], bl4[sub * 2 + 1]);
                    mma16816(c, pl[0], pl[1], pl[2], pl[3],
                             bh4[sub * 2], bh4[sub * 2 + 1]);
                }
            }
        }
    }

    /* ---- epilogue: normalize, write fp32 ao ---- */
    const float i0 = 1.f / lrow0;
    const float i1 = 1.f / lrow1;
    const int r0 = qt * 128 + w * 16 + (lane >> 2);
    const size_t base0 = ((size_t)b * N_ + r0) * D_ + h * DH_ + (lane & 3) * 2;
    const size_t base1 = base0 + 8 * D_;
#pragma unroll
    for (int nt = 0; nt < 8; nt++) {
        *reinterpret_cast<float2*>(g_ao + base0 + nt * 8) =
            make_float2(o[nt][0] * i0, o[nt][1] * i0);
        *reinterpret_cast<float2*>(g_ao + base1 + nt * 8) =
            make_float2(o[nt][2] * i1, o[nt][3] * i1);
    }
}

/* ------------------------------------------------------------------ */
extern "C" void kernel_launch(void* const* d_in, const int* in_sizes, int n_in,
                              void* d_out, int out_size)
{
    const float* x    = (const float*)d_in[0];
    /* d_in[1] = mask (static causal structure, unused) */
    const float* Wqkv = (const float*)d_in[2];
    const float* Wout = (const float*)d_in[3];
    float* out = (float*)d_out;

    float* ao_ptr = nullptr;
    cudaGetSymbolAddress((void**)&ao_ptr, g_ao);

    cudaFuncSetAttribute(gemm_tf32<0>,
                         cudaFuncAttributeMaxDynamicSharedMemorySize, GEMM_SMEM);
    cudaFuncSetAttribute(gemm_tf32<1>,
                         cudaFuncAttributeMaxDynamicSharedMemorySize, GEMM_SMEM);

    /* 1. QKV projection (tf32) -> q/k/v bf16 hi/lo (q pre-scaled) */
    gemm_tf32<0><<<dim3(3072 / 128, 4096 / 128), 256, GEMM_SMEM>>>(
        x, Wqkv, nullptr, D_, 3 * D_);

    /* 2. causal flash attention (bf16 hi/lo) -> fp32 ao */
    const int ATT_SMEM = ATT_SMEM_ELEMS * (int)sizeof(__nv_bfloat16);
    cudaFuncSetAttribute(attn_mma,
                         cudaFuncAttributeMaxDynamicSharedMemorySize, ATT_SMEM);
    attn_mma<<<dim3((N_ / 128) * 32), 256, ATT_SMEM>>>();

    /* 3. output projection (tf32) -> d_out (fp32) */
    gemm_tf32<1><<<dim3(1024 / 128, 4096 / 128), 256, GEMM_SMEM>>>(
        ao_ptr, Wout, out, D_, D_);
}

// round 11
// speedup vs baseline: 2.5294x; 1.0576x over previous
#include <cuda_runtime.h>
#include <cuda_bf16.h>
#include <math.h>
#include <stdint.h>

#define B_ 2
#define N_ 2048
#define D_ 1024
#define H_ 16
#define DH_ 64
#define SCALE_ 0.125f   /* 64^-0.5, exact power of two */

/* ------------------------------------------------------------------ */
/* device scratch                                                      */
/* ------------------------------------------------------------------ */
__device__ float g_xr [4096 * 1024];   /* tf32-rounded x      */
__device__ float g_wqr[3072 * 1024];   /* tf32-rounded W_qkv  */
__device__ float g_wor[1024 * 1024];   /* tf32-rounded W_out  */
__device__ __nv_bfloat16 g_qh[B_*H_*N_*DH_], g_ql[B_*H_*N_*DH_];
__device__ __nv_bfloat16 g_kh[B_*H_*N_*DH_], g_kl[B_*H_*N_*DH_];
__device__ __nv_bfloat16 g_vh[B_*H_*N_*DH_], g_vl[B_*H_*N_*DH_];
__device__ float         g_ao [B_*N_*D_];
__device__ float         g_aor[B_*N_*D_];  /* tf32-rounded ao */

/* ------------------------------------------------------------------ */
/* helpers                                                             */
/* ------------------------------------------------------------------ */
__device__ __forceinline__ uint32_t smem_u32(const void* p) {
    uint32_t a;
    asm("{ .reg .u64 t; cvta.to.shared.u64 t, %1; cvt.u32.u64 %0, t; }"
        : "=r"(a) : "l"(p));
    return a;
}

/* swizzle for 128B-row fp32 tiles: chunk' = chunk ^ (row & 7) */
__device__ __forceinline__ uint32_t swzA(uint32_t o) {
    return o ^ (((o >> 7) & 7u) << 4);
}

__device__ __forceinline__ void ldsm4(uint32_t addr, uint32_t& r0, uint32_t& r1,
                                      uint32_t& r2, uint32_t& r3) {
    asm volatile("ldmatrix.sync.aligned.m8n8.x4.shared.b16 {%0,%1,%2,%3}, [%4];"
                 : "=r"(r0), "=r"(r1), "=r"(r2), "=r"(r3) : "r"(addr));
}

__device__ __forceinline__ void ldsm4t(uint32_t addr, uint32_t& r0, uint32_t& r1,
                                       uint32_t& r2, uint32_t& r3) {
    asm volatile("ldmatrix.sync.aligned.m8n8.x4.trans.shared.b16 {%0,%1,%2,%3}, [%4];"
                 : "=r"(r0), "=r"(r1), "=r"(r2), "=r"(r3) : "r"(addr));
}

__device__ __forceinline__ void mma16816(float* c,
                                         uint32_t a0, uint32_t a1, uint32_t a2, uint32_t a3,
                                         uint32_t b0, uint32_t b1) {
    asm volatile(
        "mma.sync.aligned.m16n8k16.row.col.f32.bf16.bf16.f32 "
        "{%0,%1,%2,%3}, {%4,%5,%6,%7}, {%8,%9}, {%0,%1,%2,%3};"
        : "+f"(c[0]), "+f"(c[1]), "+f"(c[2]), "+f"(c[3])
        : "r"(a0), "r"(a1), "r"(a2), "r"(a3), "r"(b0), "r"(b1));
}

__device__ __forceinline__ void mma_tf32(float* c,
                                         uint32_t a0, uint32_t a1, uint32_t a2, uint32_t a3,
                                         uint32_t b0, uint32_t b1) {
    asm volatile(
        "mma.sync.aligned.m16n8k8.row.col.f32.tf32.tf32.f32 "
        "{%0,%1,%2,%3}, {%4,%5,%6,%7}, {%8,%9}, {%0,%1,%2,%3};"
        : "+f"(c[0]), "+f"(c[1]), "+f"(c[2]), "+f"(c[3])
        : "r"(a0), "r"(a1), "r"(a2), "r"(a3), "r"(b0), "r"(b1));
}

__device__ __forceinline__ void split2(float x, float y, uint32_t& hi, uint32_t& lo) {
    __nv_bfloat162 h = __floats2bfloat162_rn(x, y);
    float rx = x - __bfloat162float(h.x);
    float ry = y - __bfloat162float(h.y);
    __nv_bfloat162 l = __floats2bfloat162_rn(rx, ry);
    hi = *reinterpret_cast<uint32_t*>(&h);
    lo = *reinterpret_cast<uint32_t*>(&l);
}

__device__ __forceinline__ void cp16(uint32_t saddr, const void* g) {
    asm volatile("cp.async.cg.shared.global [%0], [%1], 16;"
                 :: "r"(saddr), "l"(g) : "memory");
}
__device__ __forceinline__ void cp_commit() {
    asm volatile("cp.async.commit_group;" ::: "memory");
}
template <int NN>
__device__ __forceinline__ void cp_wait() {
    asm volatile("cp.async.wait_group %0;" :: "n"(NN) : "memory");
}

/* ------------------------------------------------------------------ */
/* round kernel: fp32 -> tf32-rounded fp32 (rna)                       */
/* ------------------------------------------------------------------ */
__global__ void __launch_bounds__(256)
round_tf32(const float* __restrict__ src, float* __restrict__ dst, int n4)
{
    int i      = blockIdx.x * blockDim.x + threadIdx.x;
    int stride = gridDim.x * blockDim.x;
    for (; i < n4; i += stride) {
        float4 v = reinterpret_cast<const float4*>(src)[i];
        float4 r;
        asm("cvt.rna.tf32.f32 %0, %1;" : "=r"(*(uint32_t*)&r.x) : "f"(v.x));
        asm("cvt.rna.tf32.f32 %0, %1;" : "=r"(*(uint32_t*)&r.y) : "f"(v.y));
        asm("cvt.rna.tf32.f32 %0, %1;" : "=r"(*(uint32_t*)&r.z) : "f"(v.z));
        asm("cvt.rna.tf32.f32 %0, %1;" : "=r"(*(uint32_t*)&r.w) : "f"(v.w));
        reinterpret_cast<float4*>(dst)[i] = r;
    }
}

/* ------------------------------------------------------------------ */
/* TF32 HMMA GEMM on pre-rounded fp32: C = A * W^T.                    */
/* tile 128x128, BK=32, 256 thr (8 warps 4x2), 2 CTAs/SM.              */
/* 3-stage cp.async pipeline; swizzled pad-free smem. NO inner cvt.    */
/* MODE 0: epilogue -> q/k/v bf16 hi/lo (q scaled). MODE 1: fp32 C.    */
/* ------------------------------------------------------------------ */
#define GARR_B (128 * 128u)                 /* bytes per fp32 array (16 KB) */
#define GSTAGE_B (2 * GARR_B)               /* bytes per stage (32 KB)      */
#define GEMM_SMEM (3 * GSTAGE_B)            /* 98304 B dynamic              */

template <int MODE>
__global__ void __launch_bounds__(256, 2)
gemm_tf32(const float* __restrict__ A, const float* __restrict__ W,
          float* __restrict__ C, int K, int Nout)
{
    extern __shared__ float smem[];
    const uint32_t sb = smem_u32(smem);

    const int tid  = threadIdx.x;
    const int lane = tid & 31;
    const int wid  = tid >> 5;
    const int wm   = wid & 3;
    const int wn   = wid >> 2;

    const int m0 = blockIdx.y * 128;
    const int j0 = blockIdx.x * 128;

    const int q0 = tid & 7;

#define ISSUE_CHUNK(kc, stage)                                                \
    do {                                                                      \
        const int koff = (kc) * 32;                                          \
        const uint32_t st_ = sb + (uint32_t)(stage) * GSTAGE_B;              \
        _Pragma("unroll")                                                     \
        for (int i_ = 0; i_ < 4; i_++) {                                     \
            int r_ = (tid + i_ * 256) >> 3;                                  \
            uint32_t so_ = swzA((uint32_t)(r_ * 128 + q0 * 16));             \
            cp16(st_ + so_,          A + (size_t)(m0 + r_) * K + koff + q0 * 4); \
            cp16(st_ + GARR_B + so_, W + (size_t)(j0 + r_) * K + koff + q0 * 4); \
        }                                                                     \
        cp_commit();                                                         \
    } while (0)

    /* ldsm lane address components */
    const int a_r8 = lane & 7;
    const int a_rh = (lane >> 3) & 1;
    const int a_ch = lane >> 4;
    const int b_rh = lane >> 4;
    const int b_ch = (lane >> 3) & 1;

    float acc[2][8][4];
#pragma unroll
    for (int i = 0; i < 2; i++)
#pragma unroll
        for (int j = 0; j < 8; j++)
#pragma unroll
            for (int c = 0; c < 4; c++) acc[i][j][c] = 0.f;

    const int nchunk = K >> 5;

    ISSUE_CHUNK(0, 0);
    ISSUE_CHUNK(1, 1);

    for (int kc = 0; kc < nchunk; kc++) {
        cp_wait<1>();
        __syncthreads();
        if (kc + 2 < nchunk) {
            int st = kc + 2;
            ISSUE_CHUNK(st, st - (st / 3) * 3);
        }

        const uint32_t stg = sb + (uint32_t)(kc - (kc / 3) * 3) * GSTAGE_B;
        const uint32_t sA  = stg;
        const uint32_t sW  = stg + GARR_B;

#pragma unroll
        for (int ks = 0; ks < 4; ks++) {       /* k8 steps within BK=32 */
            uint32_t a[2][4];
#pragma unroll
            for (int mt = 0; mt < 2; mt++) {
                int row   = wm * 32 + mt * 16 + a_r8 + a_rh * 8;
                int chunk = ks * 2 + a_ch;
                uint32_t addr = sA + swzA((uint32_t)(row * 128 + chunk * 16));
                ldsm4(addr, a[mt][0], a[mt][1], a[mt][2], a[mt][3]);
            }
#pragma unroll
            for (int np = 0; np < 4; np++) {
                int row   = wn * 64 + np * 16 + a_r8 + b_rh * 8;
                int chunk = ks * 2 + b_ch;
                uint32_t addr = sW + swzA((uint32_t)(row * 128 + chunk * 16));
                uint32_t bfr[4];
                ldsm4(addr, bfr[0], bfr[1], bfr[2], bfr[3]);
#pragma unroll
                for (int mt = 0; mt < 2; mt++) {
                    mma_tf32(acc[mt][np * 2 + 0], a[mt][0], a[mt][1], a[mt][2], a[mt][3],
                             bfr[0], bfr[1]);
                    mma_tf32(acc[mt][np * 2 + 1], a[mt][0], a[mt][1], a[mt][2], a[mt][3],
                             bfr[2], bfr[3]);
                }
            }
        }
    }

    /* epilogue */
    const int grp = lane >> 2;
    const int qid = lane & 3;
#pragma unroll
    for (int mt = 0; mt < 2; mt++) {
#pragma unroll
        for (int nt = 0; nt < 8; nt++) {
            const float* c = acc[mt][nt];
            int row = m0 + wm * 32 + mt * 16 + grp;
            int col = j0 + wn * 64 + nt * 8 + qid * 2;
#pragma unroll
            for (int half = 0; half < 2; half++) {
                int m = row + half * 8;
                float vx = c[half * 2], vy = c[half * 2 + 1];
                if (MODE == 0) {
                    int s  = col >> 10;
                    int rr = col & 1023;
                    int h  = rr >> 6;
                    int dh = rr & 63;
                    int b  = m >> 11;
                    int n  = m & 2047;
                    size_t idx = (((size_t)(b * H_ + h) * N_ + n) * DH_ + dh);
                    float sc = (s == 0) ? SCALE_ : 1.f;
                    uint32_t hi, lo;
                    split2(vx * sc, vy * sc, hi, lo);
                    __nv_bfloat16* bhp = (s == 0) ? g_qh : (s == 1) ? g_kh : g_vh;
                    __nv_bfloat16* blp = (s == 0) ? g_ql : (s == 1) ? g_kl : g_vl;
                    *reinterpret_cast<uint32_t*>(bhp + idx) = hi;
                    *reinterpret_cast<uint32_t*>(blp + idx) = lo;
                } else {
                    *reinterpret_cast<float2*>(C + (size_t)m * Nout + col) =
                        make_float2(vx, vy);
                }
            }
        }
    }
}

/* ------------------------------------------------------------------ */
/* Flash-attention (bf16 hi/lo). K/V double-buffered via cp.async;     */
/* V B-fragments via ldmatrix.trans. 2 CTAs/SM.                        */
/* Epilogue writes BOTH fp32 ao and tf32-rounded ao (for out-proj).    */
/* ------------------------------------------------------------------ */
#define ASTR 72
#define SM_QH 0
#define SM_QL (128 * ASTR)
#define SM_ST0 (2 * 128 * ASTR)
#define STG_E  (4 * 64 * ASTR)
#define OFF_KH 0
#define OFF_KL (64 * ASTR)
#define OFF_VH (2 * 64 * ASTR)
#define OFF_VL (3 * 64 * ASTR)
#define ATT_SMEM_ELEMS (SM_ST0 + 2 * STG_E)   /* 55296 bf16 = 110592 B */

__global__ void __launch_bounds__(256, 2)
attn_mma()
{
    extern __shared__ __nv_bfloat16 sbuf[];

    const int qt = (N_ / 128 - 1) - (blockIdx.x >> 5);  /* heavy tiles first */
    const int bh = blockIdx.x & 31;
    const int b  = bh >> 4;
    const int h  = bh & 15;

    const int tid  = threadIdx.x;
    const int lane = tid & 31;
    const int w    = tid >> 5;

    const __nv_bfloat16* Qbh = g_qh + (size_t)bh * N_ * DH_;
    const __nv_bfloat16* Qbl = g_ql + (size_t)bh * N_ * DH_;
    const __nv_bfloat16* Kbh = g_kh + (size_t)bh * N_ * DH_;
    const __nv_bfloat16* Kbl = g_kl + (size_t)bh * N_ * DH_;
    const __nv_bfloat16* Vbh = g_vh + (size_t)bh * N_ * DH_;
    const __nv_bfloat16* Vbl = g_vl + (size_t)bh * N_ * DH_;

    const uint32_t sB = smem_u32(sbuf);

    const int kr0 = tid >> 3;
    const int kr1 = (tid + 256) >> 3;
    const int kc8 = (tid & 7) * 8;
    const uint32_t kso0 = (uint32_t)(kr0 * ASTR + kc8) * 2;
    const uint32_t kso1 = (uint32_t)(kr1 * ASTR + kc8) * 2;

#define ISSUE_KV(jt, stage)                                                   \
    do {                                                                      \
        const size_t g0 = (size_t)((jt) * 64 + kr0) * DH_ + kc8;             \
        const size_t g1 = (size_t)((jt) * 64 + kr1) * DH_ + kc8;             \
        const uint32_t st_ = sB + (SM_ST0 + (stage) * STG_E) * 2;            \
        cp16(st_ + OFF_KH * 2 + kso0, Kbh + g0);                             \
        cp16(st_ + OFF_KH * 2 + kso1, Kbh + g1);                             \
        cp16(st_ + OFF_KL * 2 + kso0, Kbl + g0);                             \
        cp16(st_ + OFF_KL * 2 + kso1, Kbl + g1);                             \
        cp16(st_ + OFF_VH * 2 + kso0, Vbh + g0);                             \
        cp16(st_ + OFF_VH * 2 + kso1, Vbh + g1);                             \
        cp16(st_ + OFF_VL * 2 + kso0, Vbl + g0);                             \
        cp16(st_ + OFF_VL * 2 + kso1, Vbl + g1);                             \
        cp_commit();                                                         \
    } while (0)

    ISSUE_KV(0, 0);

    /* ---- load Q tile (pre-scaled, pre-split) ---- */
#pragma unroll
    for (int it = 0; it < 4; it++) {
        int idx = tid + it * 256;
        int r   = idx >> 3;
        int c8  = (idx & 7) * 8;
        size_t g = (size_t)(qt * 128 + r) * DH_ + c8;
        *reinterpret_cast<uint4*>(sbuf + SM_QH + r * ASTR + c8) =
            *reinterpret_cast<const uint4*>(Qbh + g);
        *reinterpret_cast<uint4*>(sbuf + SM_QL + r * ASTR + c8) =
            *reinterpret_cast<const uint4*>(Qbl + g);
    }
    __syncthreads();

    /* ---- Q fragments into registers ---- */
    uint32_t qh[4][4], ql[4][4];
    {
        const uint32_t a0 = sB +
            2u * ((uint32_t)((w * 16 + (lane & 15)) * ASTR) + ((lane >> 4) << 3));
#pragma unroll
        for (int ks = 0; ks < 4; ks++) {
            ldsm4(a0 + SM_QH * 2 + 2u * (ks * 16),
                  qh[ks][0], qh[ks][1], qh[ks][2], qh[ks][3]);
            ldsm4(a0 + SM_QL * 2 + 2u * (ks * 16),
                  ql[ks][0], ql[ks][1], ql[ks][2], ql[ks][3]);
        }
    }

    const uint32_t bpat = 2u * ((uint32_t)(((lane & 7) | ((lane & 16) >> 1)) * ASTR)
                                + (lane & 8));
    const uint32_t vpat = 2u * ((uint32_t)((lane & 15) * ASTR) + ((lane & 16) >> 1));

    float o[8][4];
#pragma unroll
    for (int i = 0; i < 8; i++)
#pragma unroll
        for (int c = 0; c < 4; c++) o[i][c] = 0.f;
    float mrow0 = -INFINITY, mrow1 = -INFINITY;
    float lrow0 = 0.f, lrow1 = 0.f;

    const int qglo   = qt * 128 + w * 16;
    const int ntiles = 2 * qt + 2;

    for (int jt = 0; jt < ntiles; jt++) {
        cp_wait<0>();
        __syncthreads();
        if (jt + 1 < ntiles) ISSUE_KV(jt + 1, (jt + 1) & 1);

        if (jt * 64 > qglo + 15) continue;

        const uint32_t stg = sB + (SM_ST0 + (jt & 1) * STG_E) * 2;
        const uint32_t sKH = stg + OFF_KH * 2;
        const uint32_t sKL = stg + OFF_KL * 2;
        const uint32_t sVH = stg + OFF_VH * 2;
        const uint32_t sVL = stg + OFF_VL * 2;

        /* ---- S = Q K^T ---- */
        float s[8][4];
#pragma unroll
        for (int i = 0; i < 8; i++)
#pragma unroll
            for (int c = 0; c < 4; c++) s[i][c] = 0.f;

#pragma unroll
        for (int ks = 0; ks < 4; ks++) {
#pragma unroll
            for (int np = 0; np < 4; np++) {
                const uint32_t boff = bpat + 2u * (np * 16 * ASTR + ks * 16);
                uint32_t bh4[4], bl4[4];
                ldsm4(sKH + boff, bh4[0], bh4[1], bh4[2], bh4[3]);
                ldsm4(sKL + boff, bl4[0], bl4[1], bl4[2], bl4[3]);
#pragma unroll
                for (int sub = 0; sub < 2; sub++) {
                    float* c = s[np * 2 + sub];
                    mma16816(c, qh[ks][0], qh[ks][1], qh[ks][2], qh[ks][3],
                             bh4[sub * 2], bh4[sub * 2 + 1]);
                    mma16816(c, qh[ks][0], qh[ks][1], qh[ks][2], qh[ks][3],
                             bl4[sub * 2], bl4[sub * 2 + 1]);
                    mma16816(c, ql[ks][0], ql[ks][1], ql[ks][2], ql[ks][3],
                             bh4[sub * 2], bh4[sub * 2 + 1]);
                }
            }
        }

        /* ---- causal mask ---- */
        const int r0 = qglo + (lane >> 2);
        const int r1 = r0 + 8;
        if (jt * 64 + 63 > qglo) {
            const int colb = jt * 64 + (lane & 3) * 2;
#pragma unroll
            for (int nt = 0; nt < 8; nt++) {
                int c0 = colb + nt * 8;
                if (c0 > r0)     s[nt][0] = -INFINITY;
                if (c0 + 1 > r0) s[nt][1] = -INFINITY;
                if (c0 > r1)     s[nt][2] = -INFINITY;
                if (c0 + 1 > r1) s[nt][3] = -INFINITY;
            }
        }

        /* ---- online softmax ---- */
        float mt0 = s[0][0], mt1 = s[0][2];
#pragma unroll
        for (int nt = 0; nt < 8; nt++) {
            mt0 = fmaxf(mt0, fmaxf(s[nt][0], s[nt][1]));
            mt1 = fmaxf(mt1, fmaxf(s[nt][2], s[nt][3]));
        }
        mt0 = fmaxf(mt0, __shfl_xor_sync(0xffffffffu, mt0, 1));
        mt0 = fmaxf(mt0, __shfl_xor_sync(0xffffffffu, mt0, 2));
        mt1 = fmaxf(mt1, __shfl_xor_sync(0xffffffffu, mt1, 1));
        mt1 = fmaxf(mt1, __shfl_xor_sync(0xffffffffu, mt1, 2));

        const float mn0 = fmaxf(mrow0, mt0);
        const float mn1 = fmaxf(mrow1, mt1);
        const float al0 = __expf(mrow0 - mn0);
        const float al1 = __expf(mrow1 - mn1);

        float ps0 = 0.f, ps1 = 0.f;
#pragma unroll
        for (int nt = 0; nt < 8; nt++) {
            s[nt][0] = __expf(s[nt][0] - mn0);
            s[nt][1] = __expf(s[nt][1] - mn0);
            s[nt][2] = __expf(s[nt][2] - mn1);
            s[nt][3] = __expf(s[nt][3] - mn1);
            ps0 += s[nt][0] + s[nt][1];
            ps1 += s[nt][2] + s[nt][3];
        }
        ps0 += __shfl_xor_sync(0xffffffffu, ps0, 1);
        ps0 += __shfl_xor_sync(0xffffffffu, ps0, 2);
        ps1 += __shfl_xor_sync(0xffffffffu, ps1, 1);
        ps1 += __shfl_xor_sync(0xffffffffu, ps1, 2);

        lrow0 = lrow0 * al0 + ps0;
        lrow1 = lrow1 * al1 + ps1;
#pragma unroll
        for (int nt = 0; nt < 8; nt++) {
            o[nt][0] *= al0; o[nt][1] *= al0;
            o[nt][2] *= al1; o[nt][3] *= al1;
        }
        mrow0 = mn0;
        mrow1 = mn1;

        /* ---- O += P V (V fragments via ldmatrix.trans) ---- */
#pragma unroll
        for (int ks = 0; ks < 4; ks++) {
            uint32_t ph[4], pl[4];
            split2(s[2 * ks][0],     s[2 * ks][1],     ph[0], pl[0]);
            split2(s[2 * ks][2],     s[2 * ks][3],     ph[1], pl[1]);
            split2(s[2 * ks + 1][0], s[2 * ks + 1][1], ph[2], pl[2]);
            split2(s[2 * ks + 1][2], s[2 * ks + 1][3], ph[3], pl[3]);
#pragma unroll
            for (int np = 0; np < 4; np++) {
                const uint32_t voff = vpat + 2u * (ks * 16 * ASTR + np * 16);
                uint32_t bh4[4], bl4[4];
                ldsm4t(sVH + voff, bh4[0], bh4[1], bh4[2], bh4[3]);
                ldsm4t(sVL + voff, bl4[0], bl4[1], bl4[2], bl4[3]);
#pragma unroll
                for (int sub = 0; sub < 2; sub++) {
                    float* c = o[np * 2 + sub];
                    mma16816(c, ph[0], ph[1], ph[2], ph[3],
                             bh4[sub * 2], bh4[sub * 2 + 1]);
                    mma16816(c, ph[0], ph[1], ph[2], ph[3],
                             bl4[sub * 2], bl4[sub * 2 + 1]);
                    mma16816(c, pl[0], pl[1], pl[2], pl[3],
                             bh4[sub * 2], bh4[sub * 2 + 1]);
                }
            }
        }
    }

    /* ---- epilogue: normalize, write tf32-rounded ao (for out-proj) ---- */
    const float i0 = 1.f / lrow0;
    const float i1 = 1.f / lrow1;
    const int r0 = qt * 128 + w * 16 + (lane >> 2);
    const size_t base0 = ((size_t)b * N_ + r0) * D_ + h * DH_ + (lane & 3) * 2;
    const size_t base1 = base0 + 8 * D_;
#pragma unroll
    for (int nt = 0; nt < 8; nt++) {
        float2 v0 = make_float2(o[nt][0] * i0, o[nt][1] * i0);
        float2 v1 = make_float2(o[nt][2] * i1, o[nt][3] * i1);
        asm("cvt.rna.tf32.f32 %0, %1;" : "=r"(*(uint32_t*)&v0.x) : "f"(v0.x));
        asm("cvt.rna.tf32.f32 %0, %1;" : "=r"(*(uint32_t*)&v0.y) : "f"(v0.y));
        asm("cvt.rna.tf32.f32 %0, %1;" : "=r"(*(uint32_t*)&v1.x) : "f"(v1.x));
        asm("cvt.rna.tf32.f32 %0, %1;" : "=r"(*(uint32_t*)&v1.y) : "f"(v1.y));
        *reinterpret_cast<float2*>(g_aor + base0 + nt * 8) = v0;
        *reinterpret_cast<float2*>(g_aor + base1 + nt * 8) = v1;
    }
}

/* ------------------------------------------------------------------ */
extern "C" void kernel_launch(void* const* d_in, const int* in_sizes, int n_in,
                              void* d_out, int out_size)
{
    const float* x    = (const float*)d_in[0];
    /* d_in[1] = mask (static causal structure, unused) */
    const float* Wqkv = (const float*)d_in[2];
    const float* Wout = (const float*)d_in[3];
    float* out = (float*)d_out;

    float *xr, *wqr, *wor, *aor;
    cudaGetSymbolAddress((void**)&xr,  g_xr);
    cudaGetSymbolAddress((void**)&wqr, g_wqr);
    cudaGetSymbolAddress((void**)&wor, g_wor);
    cudaGetSymbolAddress((void**)&aor, g_aor);

    /* 0. pre-round inputs to tf32 (rna) */
    round_tf32<<<1024, 256>>>(x,    xr,  4096 * 1024 / 4);
    round_tf32<<<1024, 256>>>(Wqkv, wqr, 3072 * 1024 / 4);
    round_tf32<<<512,  256>>>(Wout, wor, 1024 * 1024 / 4);

    cudaFuncSetAttribute(gemm_tf32<0>,
                         cudaFuncAttributeMaxDynamicSharedMemorySize, GEMM_SMEM);
    cudaFuncSetAttribute(gemm_tf32<1>,
                         cudaFuncAttributeMaxDynamicSharedMemorySize, GEMM_SMEM);

    /* 1. QKV projection (tf32, no inner cvt) -> q/k/v bf16 hi/lo */
    gemm_tf32<0><<<dim3(3072 / 128, 4096 / 128), 256, GEMM_SMEM>>>(
        xr, wqr, nullptr, D_, 3 * D_);

    /* 2. causal flash attention (bf16 hi/lo) -> tf32-rounded ao */
    const int ATT_SMEM = ATT_SMEM_ELEMS * (int)sizeof(__nv_bfloat16);
    cudaFuncSetAttribute(attn_mma,
                         cudaFuncAttributeMaxDynamicSharedMemorySize, ATT_SMEM);
    attn_mma<<<dim3((N_ / 128) * 32), 256, ATT_SMEM>>>();

    /* 3. output projection (tf32, no inner cvt) -> d_out (fp32) */
    gemm_tf32<1><<<dim3(1024 / 128, 4096 / 128), 256, GEMM_SMEM>>>(
        aor, wor, out, D_, D_);
}